// round 8
// baseline (speedup 1.0000x reference)
#include <cuda_runtime.h>
#include <cuda_bf16.h>
#include <math.h>
#include <stdint.h>

#define BATCH 16384
#define KC 64                       // K elements per SMEM stage
#define STAGE_BYTES 65536
#define A_HI_OFF 0
#define A_LO_OFF 16384
#define B_HI_OFF 32768
#define B_LO_OFF 49152
#define NSTAGE 3
#define GEMM_SMEM (NSTAGE * STAGE_BYTES)
#define GTHREADS 256

// ---------------- scratch (no allocations allowed) ----------------
__device__ __nv_bfloat16 g_xh[BATCH * 256],  g_xl[BATCH * 256];
__device__ __nv_bfloat16 g_h1h[BATCH * 1024], g_h1l[BATCH * 1024];
__device__ __nv_bfloat16 g_h2h[BATCH * 1024], g_h2l[BATCH * 1024];
__device__ __nv_bfloat16 g_a1h[BATCH * 512],  g_a1l[BATCH * 512];
__device__ float g_a2[BATCH * 256];
// weights, split + transposed to K-major + pre-swizzled blocked tiles
__device__ __nv_bfloat16 g_w1h[256 * 1024],      g_w1l[256 * 1024];
__device__ __nv_bfloat16 g_w2h[1024 * 1024],     g_w2l[1024 * 1024];
__device__ __nv_bfloat16 g_hw1h[4 * 1024 * 512], g_hw1l[4 * 1024 * 512];
__device__ __nv_bfloat16 g_hw2h[4 * 512 * 256],  g_hw2l[4 * 512 * 256];
__device__ int g_rowmap[BATCH];
__device__ int g_off[5];

// ---------------- helpers (baseline PTX only) ----------------
__device__ __forceinline__ uint32_t smem_u32(const void* p) {
    uint32_t a;
    asm("{ .reg .u64 t; cvta.to.shared.u64 t, %1; cvt.u32.u64 %0, t; }" : "=r"(a) : "l"(p));
    return a;
}
#define LDSM_X4(r0, r1, r2, r3, addr) \
    asm volatile("ldmatrix.sync.aligned.m8n8.x4.shared.b16 {%0,%1,%2,%3}, [%4];" \
                 : "=r"(r0), "=r"(r1), "=r"(r2), "=r"(r3) : "r"(addr))
#define CP16(dst, src) \
    asm volatile("cp.async.cg.shared.global [%0], [%1], 16;" :: "r"(dst), "l"(src) : "memory")
#define CP_COMMIT() asm volatile("cp.async.commit_group;" ::: "memory")
#define CP_WAIT1() asm volatile("cp.async.wait_group 1;" ::: "memory")
#define CP_WAIT0() asm volatile("cp.async.wait_group 0;" ::: "memory")

__device__ __forceinline__ void mma_bf16(float* d, const uint32_t* a, uint32_t b0, uint32_t b1) {
    asm volatile(
        "mma.sync.aligned.m16n8k16.row.col.f32.bf16.bf16.f32 "
        "{%0,%1,%2,%3}, {%4,%5,%6,%7}, {%8,%9}, {%0,%1,%2,%3};"
        : "+f"(d[0]), "+f"(d[1]), "+f"(d[2]), "+f"(d[3])
        : "r"(a[0]), "r"(a[1]), "r"(a[2]), "r"(a[3]), "r"(b0), "r"(b1));
}
__device__ __forceinline__ uint32_t pack2(__nv_bfloat16 a, __nv_bfloat16 b) {
    return ((uint32_t)__bfloat16_as_ushort(b) << 16) | (uint32_t)__bfloat16_as_ushort(a);
}
__device__ __forceinline__ uint32_t swz(uint32_t off) { return off ^ ((off >> 3) & 0x70); }

// ---------------- prep: combo partitioning (one block, warp-aggregated) -------
__global__ void partition_k(const int* __restrict__ flags) {
    __shared__ int soff[4];
    const int tid = threadIdx.x;
    const int lane = tid & 31;

    if (tid < 4) soff[tid] = 0;
    __syncthreads();
    for (int i = tid; i < BATCH; i += 1024) {
        int c = flags[2 * i] * 2 + flags[2 * i + 1];
        unsigned same = __match_any_sync(0xFFFFFFFFu, c);
        int leader = __ffs(same) - 1;
        if (lane == leader) atomicAdd(&soff[c], __popc(same));
    }
    __syncthreads();
    if (tid == 0) {
        int o = 0;
        #pragma unroll
        for (int c = 0; c < 4; c++) { int n = soff[c]; g_off[c] = o; soff[c] = o; o += n; }
        g_off[4] = o;
    }
    __syncthreads();
    for (int i = tid; i < BATCH; i += 1024) {
        int c = flags[2 * i] * 2 + flags[2 * i + 1];
        unsigned same = __match_any_sync(0xFFFFFFFFu, c);
        int leader = __ffs(same) - 1;
        int rank = __popc(same & ((1u << lane) - 1u));
        int base = 0;
        if (lane == leader) base = atomicAdd(&soff[c], __popc(same));
        base = __shfl_sync(0xFFFFFFFFu, base, leader);
        g_rowmap[base + rank] = i;
    }
}

// ---------------- prep: split x ----------------
__global__ void splitX_k(const float* __restrict__ x) {
    int idx = blockIdx.x * blockDim.x + threadIdx.x;
    if (idx >= BATCH * 256 / 4) return;
    float4 v = *(const float4*)(x + (size_t)idx * 4);
    __nv_bfloat16 h0 = __float2bfloat16(v.x), h1 = __float2bfloat16(v.y);
    __nv_bfloat16 h2 = __float2bfloat16(v.z), h3 = __float2bfloat16(v.w);
    __nv_bfloat16 l0 = __float2bfloat16(v.x - __bfloat162float(h0));
    __nv_bfloat16 l1 = __float2bfloat16(v.y - __bfloat162float(h1));
    __nv_bfloat16 l2 = __float2bfloat16(v.z - __bfloat162float(h2));
    __nv_bfloat16 l3 = __float2bfloat16(v.w - __bfloat162float(h3));
    *(uint2*)(g_xh + (size_t)idx * 4) = make_uint2(pack2(h0, h1), pack2(h2, h3));
    *(uint2*)(g_xl + (size_t)idx * 4) = make_uint2(pack2(l0, l1), pack2(l2, l3));
}

// ---------------- prep: split + transpose + swizzle all weights ----------------
__global__ void splitW_k(const float* __restrict__ W1, const float* __restrict__ W2,
                         const float* __restrict__ HW1, const float* __restrict__ HW2) {
    int z = blockIdx.z;
    int K, N, C;
    const float* src;
    __nv_bfloat16 *dh, *dl;
    if (z == 0)      { K = 256;  N = 1024; C = 1; src = W1;  dh = g_w1h;  dl = g_w1l; }
    else if (z == 1) { K = 1024; N = 1024; C = 1; src = W2;  dh = g_w2h;  dl = g_w2l; }
    else if (z == 2) { K = 1024; N = 512;  C = 4; src = HW1; dh = g_hw1h; dl = g_hw1l; }
    else             { K = 512;  N = 256;  C = 4; src = HW2; dh = g_hw2h; dl = g_hw2l; }
    const int kg = K >> 3;
    int idx = blockIdx.x * blockDim.x + threadIdx.x;
    if (idx >= C * N * kg) return;
    const int n_ = idx % N;
    const int t  = idx / N;
    const int k8 = (t % kg) * 8;
    const int c  = t / kg;

    const float* s = src + ((size_t)c * K + k8) * N + n_;
    __nv_bfloat16 hb[8], lb[8];
    #pragma unroll
    for (int j = 0; j < 8; j++) {
        float v = s[(size_t)j * N];
        hb[j] = __float2bfloat16(v);
        lb[j] = __float2bfloat16(v - __bfloat162float(hb[j]));
    }
    const int nt = n_ >> 7, rr = n_ & 127, kt = k8 >> 6, kk = k8 & 63;
    const size_t base = (((size_t)c * (N >> 7) + nt) * (K >> 6) + kt) * 8192;
    const uint32_t sw = swz((uint32_t)rr * 128 + kk * 2);
    *(uint4*)((char*)(dh + base) + sw) = *(uint4*)hb;
    *(uint4*)((char*)(dl + base) + sw) = *(uint4*)lb;
}

// ---------------- warp-MMA bf16x3 GEMM (256 thr, 8 warps, 64x32 tiles) --------
// MODE: 0 dense, 1 gather via g_rowmap, 2 compact
// ASRC: 0 g_x pair, 1 g_h1 pair, 2 g_h2 pair, 3 g_a1 pair
// WSRC: 0 w1, 1 w2, 2 hw1, 3 hw2
// DST : 0 g_h1 pair, 1 g_h2 pair, 2 g_a1 pair, 3 g_a2 fp32
template <int MODE, int ASRC, int WSRC, int DST, int K, int N>
__global__ __launch_bounds__(GTHREADS, 1)
void gemm_mma(const float* __restrict__ Bias)
{
    extern __shared__ __align__(1024) char smem[];
    constexpr int NK = K / KC;
    const int tid = threadIdx.x;
    const int c = blockIdx.z;

    int mstart, mend;
    if (MODE == 0) { mstart = 0; mend = BATCH; }
    else           { mstart = g_off[c]; mend = g_off[c + 1]; }
    const int m0 = mstart + blockIdx.y * 128;
    if (m0 >= mend) return;
    const int n0 = blockIdx.x * 128;

    const float* bc = Bias + (size_t)c * N;
    const uint32_t smb = smem_u32(smem);

    // ---- source pointers ----
    const __nv_bfloat16 *Abh, *Abl;
    if (ASRC == 0)      { Abh = g_xh;  Abl = g_xl; }
    else if (ASRC == 1) { Abh = g_h1h; Abl = g_h1l; }
    else if (ASRC == 2) { Abh = g_h2h; Abl = g_h2l; }
    else                { Abh = g_a1h; Abl = g_a1l; }
    const __nv_bfloat16 *Wbh, *Wbl;
    if (WSRC == 0)      { Wbh = g_w1h;  Wbl = g_w1l; }
    else if (WSRC == 1) { Wbh = g_w2h;  Wbl = g_w2l; }
    else if (WSRC == 2) { Wbh = g_hw1h; Wbl = g_hw1l; }
    else                { Wbh = g_hw2h; Wbl = g_hw2l; }
    const size_t wtile0 = (((size_t)c * (N >> 7) + blockIdx.x) * (K >> 6)) * 8192;
    const __nv_bfloat16* Wth = Wbh + wtile0;
    const __nv_bfloat16* Wtl = Wbl + wtile0;

    // ---- A loader mapping: 2 threads per row, 64B (32 elems) each ----
    const int ar = tid >> 1;          // 0..127
    const int aq = tid & 1;
    int apos = m0 + ar;
    if (apos > mend - 1) apos = mend - 1;
    const int grow = (MODE == 1) ? g_rowmap[apos] : apos;
    const __nv_bfloat16* Arh = Abh + (size_t)grow * K + aq * 32;
    const __nv_bfloat16* Arl = Abl + (size_t)grow * K + aq * 32;
    const uint32_t a_sw_base = (uint32_t)ar * 128 + aq * 64;

    auto issue = [&](int kc) {
        const int s = kc % NSTAGE;
        const uint32_t stb = smb + s * STAGE_BYTES;
        const int k0 = kc * KC;
        #pragma unroll
        for (int j = 0; j < 4; j++) {
            uint32_t sw = swz(a_sw_base + j * 16);
            CP16(stb + A_HI_OFF + sw, Arh + k0 + j * 8);
            CP16(stb + A_LO_OFF + sw, Arl + k0 + j * 8);
        }
        const __nv_bfloat16* wh = Wth + (size_t)kc * 8192 + tid * 32;
        const __nv_bfloat16* wl = Wtl + (size_t)kc * 8192 + tid * 32;
        #pragma unroll
        for (int j = 0; j < 4; j++) {
            CP16(stb + B_HI_OFF + tid * 64 + j * 16, wh + j * 8);
            CP16(stb + B_LO_OFF + tid * 64 + j * 16, wl + j * 8);
        }
        CP_COMMIT();
    };

    // ---- warp MMA state: 8 warps in 2(m) x 4(n) grid, warp tile 64x32 ----
    const int wid = tid >> 5;
    const int lane = tid & 31;
    const int wm = (wid >> 2) * 64;   // 2 m bands
    const int wn = (wid & 3) * 32;    // 4 n bands

    float acc[4][4][4];   // [m16 frag][n8 frag][quad regs]
    #pragma unroll
    for (int i = 0; i < 4; i++)
        #pragma unroll
        for (int j = 0; j < 4; j++)
            #pragma unroll
            for (int q = 0; q < 4; q++) acc[i][j][q] = 0.0f;

    const int mat = lane >> 3, rin = lane & 7;
    const int a_row = ((mat & 1) << 3) + rin;
    const int a_kh  = (mat >> 1) << 3;
    const int b_row = ((mat >> 1) << 3) + rin;
    const int b_kh  = (mat & 1) << 3;

    // fragment double buffers
    uint32_t ah[2][4][4], al[2][4][4], bh[2][2][4], bl[2][2][4];

    auto ldfrags = [&](int s, int k16, int buf) {
        const uint32_t aHi = smb + s * STAGE_BYTES + A_HI_OFF;
        const uint32_t aLo = smb + s * STAGE_BYTES + A_LO_OFF;
        const uint32_t bHi = smb + s * STAGE_BYTES + B_HI_OFF;
        const uint32_t bLo = smb + s * STAGE_BYTES + B_LO_OFF;
        const int kh = k16 * 16;
        #pragma unroll
        for (int mi = 0; mi < 4; mi++) {
            uint32_t sw = swz((uint32_t)(wm + mi * 16 + a_row) * 128 + (kh + a_kh) * 2);
            LDSM_X4(ah[buf][mi][0], ah[buf][mi][1], ah[buf][mi][2], ah[buf][mi][3], aHi + sw);
            LDSM_X4(al[buf][mi][0], al[buf][mi][1], al[buf][mi][2], al[buf][mi][3], aLo + sw);
        }
        #pragma unroll
        for (int nf = 0; nf < 2; nf++) {
            uint32_t sw = swz((uint32_t)(wn + nf * 16 + b_row) * 128 + (kh + b_kh) * 2);
            LDSM_X4(bh[buf][nf][0], bh[buf][nf][1], bh[buf][nf][2], bh[buf][nf][3], bHi + sw);
            LDSM_X4(bl[buf][nf][0], bl[buf][nf][1], bl[buf][nf][2], bl[buf][nf][3], bLo + sw);
        }
    };

    auto mmablock = [&](int buf) {
        #pragma unroll
        for (int mi = 0; mi < 4; mi++)
            #pragma unroll
            for (int nf = 0; nf < 2; nf++)
                #pragma unroll
                for (int nn = 0; nn < 2; nn++) {
                    float* d = acc[mi][nf * 2 + nn];
                    mma_bf16(d, ah[buf][mi], bh[buf][nf][nn * 2], bh[buf][nf][nn * 2 + 1]);
                    mma_bf16(d, al[buf][mi], bh[buf][nf][nn * 2], bh[buf][nf][nn * 2 + 1]);
                    mma_bf16(d, ah[buf][mi], bl[buf][nf][nn * 2], bl[buf][nf][nn * 2 + 1]);
                }
    };

    // ---- 3-stage cp.async pipeline + k16 fragment double-buffer ----
    issue(0); issue(1);
    for (int kc = 0; kc < NK; kc++) {
        const int s = kc % NSTAGE;
        if (kc + 2 < NK) { CP_WAIT1(); } else { CP_WAIT0(); }
        __syncthreads();
        if (kc + 2 < NK) issue(kc + 2);
        ldfrags(s, 0, 0);
        #pragma unroll
        for (int k16 = 0; k16 < KC / 16; k16++) {
            if (k16 + 1 < KC / 16) ldfrags(s, k16 + 1, (k16 + 1) & 1);
            mmablock(k16 & 1);
        }
    }

    // ---- epilogue ----
    __nv_bfloat16 *Oh = nullptr, *Ol = nullptr;
    if (DST == 0) { Oh = g_h1h; Ol = g_h1l; }
    else if (DST == 1) { Oh = g_h2h; Ol = g_h2l; }
    else if (DST == 2) { Oh = g_a1h; Ol = g_a1l; }

    const int qrow = lane >> 2;
    const int qcol = (lane & 3) * 2;
    #pragma unroll
    for (int mi = 0; mi < 4; mi++) {
        #pragma unroll
        for (int half = 0; half < 2; half++) {
            const int m = m0 + wm + mi * 16 + qrow + half * 8;
            if (MODE != 0 && m >= mend) continue;
            #pragma unroll
            for (int nj = 0; nj < 4; nj++) {
                const int col = n0 + wn + nj * 8 + qcol;
                float v0 = acc[mi][nj][half * 2 + 0] + __ldg(bc + col);
                float v1 = acc[mi][nj][half * 2 + 1] + __ldg(bc + col + 1);
                v0 = fmaxf(v0, 0.0f); v1 = fmaxf(v1, 0.0f);
                if (DST == 3) {
                    *(float2*)(g_a2 + (size_t)m * N + col) = make_float2(v0, v1);
                } else {
                    __nv_bfloat16 h0 = __float2bfloat16(v0), h1 = __float2bfloat16(v1);
                    __nv_bfloat16 l0 = __float2bfloat16(v0 - __bfloat162float(h0));
                    __nv_bfloat16 l1 = __float2bfloat16(v1 - __bfloat162float(h1));
                    size_t o = (size_t)m * N + col;
                    *(uint32_t*)(Oh + o) = pack2(h0, h1);
                    *(uint32_t*)(Ol + o) = pack2(l0, l1);
                }
            }
        }
    }
}

// ---------------- final head (dot 256 + bias + sigmoid + scatter) ----------------
__global__ void head3_k(const float* __restrict__ HW3,
                        const float* __restrict__ Hb3,
                        float* __restrict__ out)
{
    int gwarp = (blockIdx.x * blockDim.x + threadIdx.x) >> 5;
    int lane = threadIdx.x & 31;
    if (gwarp >= BATCH) return;

    int c;
    if (gwarp < g_off[1]) c = 0;
    else if (gwarp < g_off[2]) c = 1;
    else if (gwarp < g_off[3]) c = 2;
    else c = 3;

    const float* a = g_a2 + (size_t)gwarp * 256;
    const float* w = HW3 + (size_t)c * 256;

    float s = 0.0f;
    #pragma unroll
    for (int j = lane; j < 256; j += 32) s = fmaf(a[j], w[j], s);
    #pragma unroll
    for (int o = 16; o; o >>= 1) s += __shfl_xor_sync(0xFFFFFFFFu, s, o);

    if (lane == 0) {
        s += Hb3[c];
        out[g_rowmap[gwarp]] = 1.0f / (1.0f + expf(-s));
    }
}

// ---------------- launch ----------------
extern "C" void kernel_launch(void* const* d_in, const int* in_sizes, int n_in,
                              void* d_out, int out_size)
{
    const float* x     = (const float*)d_in[0];
    const int*   flags = (const int*)  d_in[1];
    const float* W1    = (const float*)d_in[2];
    const float* b1    = (const float*)d_in[3];
    const float* W2    = (const float*)d_in[4];
    const float* b2    = (const float*)d_in[5];
    const float* HW1   = (const float*)d_in[6];
    const float* Hb1   = (const float*)d_in[7];
    const float* HW2   = (const float*)d_in[8];
    const float* Hb2   = (const float*)d_in[9];
    const float* HW3   = (const float*)d_in[10];
    const float* Hb3   = (const float*)d_in[11];
    float* out = (float*)d_out;

    cudaFuncSetAttribute(gemm_mma<0, 0, 0, 0, 256, 1024>,
                         cudaFuncAttributeMaxDynamicSharedMemorySize, GEMM_SMEM);
    cudaFuncSetAttribute(gemm_mma<0, 1, 1, 1, 1024, 1024>,
                         cudaFuncAttributeMaxDynamicSharedMemorySize, GEMM_SMEM);
    cudaFuncSetAttribute(gemm_mma<1, 2, 2, 2, 1024, 512>,
                         cudaFuncAttributeMaxDynamicSharedMemorySize, GEMM_SMEM);
    cudaFuncSetAttribute(gemm_mma<2, 3, 3, 3, 512, 256>,
                         cudaFuncAttributeMaxDynamicSharedMemorySize, GEMM_SMEM);

    // prep
    partition_k<<<1, 1024>>>(flags);
    splitX_k<<<BATCH * 256 / 4 / 256, 256>>>(x);
    splitW_k<<<dim3(1024, 1, 4), 256>>>(W1, W2, HW1, HW2);

    // trunk L1: [16384,256] @ [256,1024] -> h1 pair
    gemm_mma<0, 0, 0, 0, 256, 1024><<<dim3(8, 128, 1), GTHREADS, GEMM_SMEM>>>(b1);
    // trunk L2: [16384,1024] @ [1024,1024] -> h2 pair
    gemm_mma<0, 1, 1, 1, 1024, 1024><<<dim3(8, 128, 1), GTHREADS, GEMM_SMEM>>>(b2);
    // head L1 (gather per-combo): [cnt_c,1024] @ HW1[c][1024,512] -> a1 pair
    gemm_mma<1, 2, 2, 2, 1024, 512><<<dim3(4, 128, 4), GTHREADS, GEMM_SMEM>>>(Hb1);
    // head L2 (compact per-combo): [cnt_c,512] @ HW2[c][512,256] -> a2 fp32
    gemm_mma<2, 3, 3, 3, 512, 256><<<dim3(2, 128, 4), GTHREADS, GEMM_SMEM>>>(Hb2);

    head3_k<<<(BATCH * 32) / 256, 256>>>(HW3, Hb3, out);
}

// round 9
// speedup vs baseline: 1.5697x; 1.5697x over previous
#include <cuda_runtime.h>
#include <cuda_fp16.h>
#include <math.h>
#include <stdint.h>

#define BATCH 16384
#define KC 64                       // K elements per SMEM stage
#define STAGE_BYTES 49152
#define A_HI_OFF 0
#define A_LO_OFF 16384
#define B_HI_OFF 32768
#define NSTAGE 3
#define GEMM_SMEM (NSTAGE * STAGE_BYTES)
#define GTHREADS 512

// ---------------- scratch (no allocations allowed) ----------------
__device__ __half g_xh[BATCH * 256],  g_xl[BATCH * 256];
__device__ __half g_h1h[BATCH * 1024], g_h1l[BATCH * 1024];
__device__ __half g_h2h[BATCH * 1024], g_h2l[BATCH * 1024];
__device__ __half g_a1h[BATCH * 512],  g_a1l[BATCH * 512];
__device__ float g_a2[BATCH * 256];
// weights: single fp16, transposed to K-major + pre-swizzled blocked tiles
__device__ __half g_w1h[256 * 1024];
__device__ __half g_w2h[1024 * 1024];
__device__ __half g_hw1h[4 * 1024 * 512];
__device__ __half g_hw2h[4 * 512 * 256];
__device__ int g_rowmap[BATCH];
__device__ int g_off[5];

// ---------------- helpers (baseline PTX only) ----------------
__device__ __forceinline__ uint32_t smem_u32(const void* p) {
    uint32_t a;
    asm("{ .reg .u64 t; cvta.to.shared.u64 t, %1; cvt.u32.u64 %0, t; }" : "=r"(a) : "l"(p));
    return a;
}
#define LDSM_X4(r0, r1, r2, r3, addr) \
    asm volatile("ldmatrix.sync.aligned.m8n8.x4.shared.b16 {%0,%1,%2,%3}, [%4];" \
                 : "=r"(r0), "=r"(r1), "=r"(r2), "=r"(r3) : "r"(addr))
#define CP16(dst, src) \
    asm volatile("cp.async.cg.shared.global [%0], [%1], 16;" :: "r"(dst), "l"(src) : "memory")
#define CP_COMMIT() asm volatile("cp.async.commit_group;" ::: "memory")
#define CP_WAIT1() asm volatile("cp.async.wait_group 1;" ::: "memory")
#define CP_WAIT0() asm volatile("cp.async.wait_group 0;" ::: "memory")

__device__ __forceinline__ void mma_fp16(float* d, const uint32_t* a, uint32_t b0, uint32_t b1) {
    asm volatile(
        "mma.sync.aligned.m16n8k16.row.col.f32.f16.f16.f32 "
        "{%0,%1,%2,%3}, {%4,%5,%6,%7}, {%8,%9}, {%0,%1,%2,%3};"
        : "+f"(d[0]), "+f"(d[1]), "+f"(d[2]), "+f"(d[3])
        : "r"(a[0]), "r"(a[1]), "r"(a[2]), "r"(a[3]), "r"(b0), "r"(b1));
}
__device__ __forceinline__ uint32_t pack2h(__half a, __half b) {
    return ((uint32_t)__half_as_ushort(b) << 16) | (uint32_t)__half_as_ushort(a);
}
__device__ __forceinline__ uint32_t swz(uint32_t off) { return off ^ ((off >> 3) & 0x70); }

// ---------------- prep: combo partitioning (one block, warp-aggregated) -------
__global__ void partition_k(const int* __restrict__ flags) {
    __shared__ int soff[4];
    const int tid = threadIdx.x;
    const int lane = tid & 31;

    if (tid < 4) soff[tid] = 0;
    __syncthreads();
    for (int i = tid; i < BATCH; i += 1024) {
        int c = flags[2 * i] * 2 + flags[2 * i + 1];
        unsigned same = __match_any_sync(0xFFFFFFFFu, c);
        int leader = __ffs(same) - 1;
        if (lane == leader) atomicAdd(&soff[c], __popc(same));
    }
    __syncthreads();
    if (tid == 0) {
        int o = 0;
        #pragma unroll
        for (int c = 0; c < 4; c++) { int n = soff[c]; g_off[c] = o; soff[c] = o; o += n; }
        g_off[4] = o;
    }
    __syncthreads();
    for (int i = tid; i < BATCH; i += 1024) {
        int c = flags[2 * i] * 2 + flags[2 * i + 1];
        unsigned same = __match_any_sync(0xFFFFFFFFu, c);
        int leader = __ffs(same) - 1;
        int rank = __popc(same & ((1u << lane) - 1u));
        int base = 0;
        if (lane == leader) base = atomicAdd(&soff[c], __popc(same));
        base = __shfl_sync(0xFFFFFFFFu, base, leader);
        g_rowmap[base + rank] = i;
    }
}

// ---------------- prep: split x into fp16 hi/lo ----------------
__global__ void splitX_k(const float* __restrict__ x) {
    int idx = blockIdx.x * blockDim.x + threadIdx.x;
    if (idx >= BATCH * 256 / 4) return;
    float4 v = *(const float4*)(x + (size_t)idx * 4);
    __half h0 = __float2half_rn(v.x), h1 = __float2half_rn(v.y);
    __half h2 = __float2half_rn(v.z), h3 = __float2half_rn(v.w);
    __half l0 = __float2half_rn(v.x - __half2float(h0));
    __half l1 = __float2half_rn(v.y - __half2float(h1));
    __half l2 = __float2half_rn(v.z - __half2float(h2));
    __half l3 = __float2half_rn(v.w - __half2float(h3));
    *(uint2*)(g_xh + (size_t)idx * 4) = make_uint2(pack2h(h0, h1), pack2h(h2, h3));
    *(uint2*)(g_xl + (size_t)idx * 4) = make_uint2(pack2h(l0, l1), pack2h(l2, l3));
}

// ---------------- prep: convert + transpose + swizzle all weights (fp16) ------
// dst blocked layout: [c][nt=N/128][kt=K/64][8192 elems] (tile: n-row 0..127 x k 0..63,
// element (rr,kk) at byte swz(rr*128 + kk*2) within the 16KB tile)
__global__ void splitW_k(const float* __restrict__ W1, const float* __restrict__ W2,
                         const float* __restrict__ HW1, const float* __restrict__ HW2) {
    int z = blockIdx.z;
    int K, N, C;
    const float* src;
    __half* dh;
    if (z == 0)      { K = 256;  N = 1024; C = 1; src = W1;  dh = g_w1h; }
    else if (z == 1) { K = 1024; N = 1024; C = 1; src = W2;  dh = g_w2h; }
    else if (z == 2) { K = 1024; N = 512;  C = 4; src = HW1; dh = g_hw1h; }
    else             { K = 512;  N = 256;  C = 4; src = HW2; dh = g_hw2h; }
    const int kg = K >> 3;
    int idx = blockIdx.x * blockDim.x + threadIdx.x;
    if (idx >= C * N * kg) return;
    const int n_ = idx % N;
    const int t  = idx / N;
    const int k8 = (t % kg) * 8;
    const int c  = t / kg;

    const float* s = src + ((size_t)c * K + k8) * N + n_;
    __half hb[8];
    #pragma unroll
    for (int j = 0; j < 8; j++) hb[j] = __float2half_rn(s[(size_t)j * N]);

    const int nt = n_ >> 7, rr = n_ & 127, kt = k8 >> 6, kk = k8 & 63;
    const size_t base = (((size_t)c * (N >> 7) + nt) * (K >> 6) + kt) * 8192;
    const uint32_t sw = swz((uint32_t)rr * 128 + kk * 2);
    *(uint4*)((char*)(dh + base) + sw) = *(uint4*)hb;
}

// ---------------- warp-MMA fp16x2 GEMM + bias + relu (512 thr, 4x4 warps) -----
// MODE: 0 dense, 1 gather via g_rowmap, 2 compact
// ASRC: 0 g_x pair, 1 g_h1 pair, 2 g_h2 pair, 3 g_a1 pair
// WSRC: 0 w1, 1 w2, 2 hw1, 3 hw2
// DST : 0 g_h1 pair, 1 g_h2 pair, 2 g_a1 pair, 3 g_a2 fp32
template <int MODE, int ASRC, int WSRC, int DST, int K, int N>
__global__ __launch_bounds__(GTHREADS, 1)
void gemm_mma(const float* __restrict__ Bias)
{
    extern __shared__ __align__(1024) char smem[];
    constexpr int NK = K / KC;
    const int tid = threadIdx.x;
    const int c = blockIdx.z;

    int mstart, mend;
    if (MODE == 0) { mstart = 0; mend = BATCH; }
    else           { mstart = g_off[c]; mend = g_off[c + 1]; }
    const int m0 = mstart + blockIdx.y * 128;
    if (m0 >= mend) return;
    const int n0 = blockIdx.x * 128;

    const float* bc = Bias + (size_t)c * N;
    const uint32_t smb = smem_u32(smem);

    // ---- source pointers ----
    const __half *Abh, *Abl;
    if (ASRC == 0)      { Abh = g_xh;  Abl = g_xl; }
    else if (ASRC == 1) { Abh = g_h1h; Abl = g_h1l; }
    else if (ASRC == 2) { Abh = g_h2h; Abl = g_h2l; }
    else                { Abh = g_a1h; Abl = g_a1l; }
    const __half* Wbh;
    if (WSRC == 0)      Wbh = g_w1h;
    else if (WSRC == 1) Wbh = g_w2h;
    else if (WSRC == 2) Wbh = g_hw1h;
    else                Wbh = g_hw2h;
    const __half* Wth = Wbh + (((size_t)c * (N >> 7) + blockIdx.x) * (K >> 6)) * 8192;

    // ---- A loader mapping: 4 threads per row, 32B (16 elems) each ----
    const int ar = tid >> 2;          // 0..127
    const int aq = tid & 3;
    int apos = m0 + ar;
    if (apos > mend - 1) apos = mend - 1;
    const int grow = (MODE == 1) ? g_rowmap[apos] : apos;
    const __half* Arh = Abh + (size_t)grow * K + aq * 16;
    const __half* Arl = Abl + (size_t)grow * K + aq * 16;
    const uint32_t a_sw_base = (uint32_t)ar * 128 + aq * 32;

    auto issue = [&](int kc) {
        const int s = kc % NSTAGE;
        const uint32_t stb = smb + s * STAGE_BYTES;
        const int k0 = kc * KC;
        #pragma unroll
        for (int j = 0; j < 2; j++) {
            uint32_t sw = swz(a_sw_base + j * 16);
            CP16(stb + A_HI_OFF + sw, Arh + k0 + j * 8);
            CP16(stb + A_LO_OFF + sw, Arl + k0 + j * 8);
        }
        const __half* wh = Wth + (size_t)kc * 8192 + tid * 16;
        #pragma unroll
        for (int j = 0; j < 2; j++)
            CP16(stb + B_HI_OFF + tid * 32 + j * 16, wh + j * 8);
        CP_COMMIT();
    };

    // ---- warp MMA state: 16 warps in 4x4 grid, warp tile 32x32 ----
    const int wid = tid >> 5;
    const int lane = tid & 31;
    const int wm = (wid & 3) * 32;
    const int wn = (wid >> 2) * 32;

    float acc[2][4][4];   // [m16 frag][n8 frag][quad regs]
    #pragma unroll
    for (int i = 0; i < 2; i++)
        #pragma unroll
        for (int j = 0; j < 4; j++)
            #pragma unroll
            for (int q = 0; q < 4; q++) acc[i][j][q] = 0.0f;

    const int mat = lane >> 3, rin = lane & 7;
    const int a_row = ((mat & 1) << 3) + rin;
    const int a_kh  = (mat >> 1) << 3;
    const int b_row = ((mat >> 1) << 3) + rin;
    const int b_kh  = (mat & 1) << 3;

    auto consume = [&](int s) {
        const uint32_t aHi = smb + s * STAGE_BYTES + A_HI_OFF;
        const uint32_t aLo = smb + s * STAGE_BYTES + A_LO_OFF;
        const uint32_t bHi = smb + s * STAGE_BYTES + B_HI_OFF;
        #pragma unroll
        for (int k16 = 0; k16 < KC / 16; k16++) {
            const int kh = k16 * 16;
            uint32_t ah[2][4], al[2][4], bh[2][4];
            #pragma unroll
            for (int mi = 0; mi < 2; mi++) {
                uint32_t sw = swz((uint32_t)(wm + mi * 16 + a_row) * 128 + (kh + a_kh) * 2);
                LDSM_X4(ah[mi][0], ah[mi][1], ah[mi][2], ah[mi][3], aHi + sw);
                LDSM_X4(al[mi][0], al[mi][1], al[mi][2], al[mi][3], aLo + sw);
            }
            #pragma unroll
            for (int nf = 0; nf < 2; nf++) {
                uint32_t sw = swz((uint32_t)(wn + nf * 16 + b_row) * 128 + (kh + b_kh) * 2);
                LDSM_X4(bh[nf][0], bh[nf][1], bh[nf][2], bh[nf][3], bHi + sw);
            }
            #pragma unroll
            for (int mi = 0; mi < 2; mi++)
                #pragma unroll
                for (int nf = 0; nf < 2; nf++)
                    #pragma unroll
                    for (int nn = 0; nn < 2; nn++) {
                        float* d = acc[mi][nf * 2 + nn];
                        mma_fp16(d, ah[mi], bh[nf][nn * 2], bh[nf][nn * 2 + 1]);
                        mma_fp16(d, al[mi], bh[nf][nn * 2], bh[nf][nn * 2 + 1]);
                    }
        }
    };

    // ---- 3-stage pipeline ----
    issue(0); issue(1);
    for (int kc = 0; kc < NK; kc++) {
        if (kc + 2 < NK) { CP_WAIT1(); } else { CP_WAIT0(); }
        __syncthreads();
        if (kc + 2 < NK) issue(kc + 2);
        consume(kc % NSTAGE);
    }

    // ---- epilogue ----
    __half *Oh = nullptr, *Ol = nullptr;
    if (DST == 0) { Oh = g_h1h; Ol = g_h1l; }
    else if (DST == 1) { Oh = g_h2h; Ol = g_h2l; }
    else if (DST == 2) { Oh = g_a1h; Ol = g_a1l; }

    const int qrow = lane >> 2;
    const int qcol = (lane & 3) * 2;
    #pragma unroll
    for (int mi = 0; mi < 2; mi++) {
        #pragma unroll
        for (int half = 0; half < 2; half++) {
            const int m = m0 + wm + mi * 16 + qrow + half * 8;
            if (MODE != 0 && m >= mend) continue;
            #pragma unroll
            for (int nj = 0; nj < 4; nj++) {
                const int col = n0 + wn + nj * 8 + qcol;
                float v0 = acc[mi][nj][half * 2 + 0] + __ldg(bc + col);
                float v1 = acc[mi][nj][half * 2 + 1] + __ldg(bc + col + 1);
                v0 = fmaxf(v0, 0.0f); v1 = fmaxf(v1, 0.0f);
                if (DST == 3) {
                    *(float2*)(g_a2 + (size_t)m * N + col) = make_float2(v0, v1);
                } else {
                    __half h0 = __float2half_rn(v0), h1 = __float2half_rn(v1);
                    __half l0 = __float2half_rn(v0 - __half2float(h0));
                    __half l1 = __float2half_rn(v1 - __half2float(h1));
                    size_t o = (size_t)m * N + col;
                    *(uint32_t*)(Oh + o) = pack2h(h0, h1);
                    *(uint32_t*)(Ol + o) = pack2h(l0, l1);
                }
            }
        }
    }
}

// ---------------- final head (dot 256 + bias + sigmoid + scatter) ----------------
__global__ void head3_k(const float* __restrict__ HW3,
                        const float* __restrict__ Hb3,
                        float* __restrict__ out)
{
    int gwarp = (blockIdx.x * blockDim.x + threadIdx.x) >> 5;
    int lane = threadIdx.x & 31;
    if (gwarp >= BATCH) return;

    int c;
    if (gwarp < g_off[1]) c = 0;
    else if (gwarp < g_off[2]) c = 1;
    else if (gwarp < g_off[3]) c = 2;
    else c = 3;

    const float* a = g_a2 + (size_t)gwarp * 256;
    const float* w = HW3 + (size_t)c * 256;

    float s = 0.0f;
    #pragma unroll
    for (int j = lane; j < 256; j += 32) s = fmaf(a[j], w[j], s);
    #pragma unroll
    for (int o = 16; o; o >>= 1) s += __shfl_xor_sync(0xFFFFFFFFu, s, o);

    if (lane == 0) {
        s += Hb3[c];
        out[g_rowmap[gwarp]] = 1.0f / (1.0f + expf(-s));
    }
}

// ---------------- launch ----------------
extern "C" void kernel_launch(void* const* d_in, const int* in_sizes, int n_in,
                              void* d_out, int out_size)
{
    const float* x     = (const float*)d_in[0];
    const int*   flags = (const int*)  d_in[1];
    const float* W1    = (const float*)d_in[2];
    const float* b1    = (const float*)d_in[3];
    const float* W2    = (const float*)d_in[4];
    const float* b2    = (const float*)d_in[5];
    const float* HW1   = (const float*)d_in[6];
    const float* Hb1   = (const float*)d_in[7];
    const float* HW2   = (const float*)d_in[8];
    const float* Hb2   = (const float*)d_in[9];
    const float* HW3   = (const float*)d_in[10];
    const float* Hb3   = (const float*)d_in[11];
    float* out = (float*)d_out;

    cudaFuncSetAttribute(gemm_mma<0, 0, 0, 0, 256, 1024>,
                         cudaFuncAttributeMaxDynamicSharedMemorySize, GEMM_SMEM);
    cudaFuncSetAttribute(gemm_mma<0, 1, 1, 1, 1024, 1024>,
                         cudaFuncAttributeMaxDynamicSharedMemorySize, GEMM_SMEM);
    cudaFuncSetAttribute(gemm_mma<1, 2, 2, 2, 1024, 512>,
                         cudaFuncAttributeMaxDynamicSharedMemorySize, GEMM_SMEM);
    cudaFuncSetAttribute(gemm_mma<2, 3, 3, 3, 512, 256>,
                         cudaFuncAttributeMaxDynamicSharedMemorySize, GEMM_SMEM);

    // prep
    partition_k<<<1, 1024>>>(flags);
    splitX_k<<<BATCH * 256 / 4 / 256, 256>>>(x);
    splitW_k<<<dim3(1024, 1, 4), 256>>>(W1, W2, HW1, HW2);

    // trunk L1: [16384,256] @ [256,1024] -> h1 pair
    gemm_mma<0, 0, 0, 0, 256, 1024><<<dim3(8, 128, 1), GTHREADS, GEMM_SMEM>>>(b1);
    // trunk L2: [16384,1024] @ [1024,1024] -> h2 pair
    gemm_mma<0, 1, 1, 1, 1024, 1024><<<dim3(8, 128, 1), GTHREADS, GEMM_SMEM>>>(b2);
    // head L1 (gather per-combo): [cnt_c,1024] @ HW1[c][1024,512] -> a1 pair
    gemm_mma<1, 2, 2, 2, 1024, 512><<<dim3(4, 128, 4), GTHREADS, GEMM_SMEM>>>(Hb1);
    // head L2 (compact per-combo): [cnt_c,512] @ HW2[c][512,256] -> a2 fp32
    gemm_mma<2, 3, 3, 3, 512, 256><<<dim3(2, 128, 4), GTHREADS, GEMM_SMEM>>>(Hb2);

    head3_k<<<(BATCH * 32) / 256, 256>>>(HW3, Hb3, out);
}

// round 10
// speedup vs baseline: 2.4581x; 1.5660x over previous
#include <cuda_runtime.h>
#include <cuda_fp16.h>
#include <math.h>
#include <stdint.h>

#define BATCH 16384
#define KC 64                       // K elements per SMEM stage
#define STAGE_BYTES 32768
#define A_OFF 0
#define B_OFF 16384
#define NSTAGE 4
#define GEMM_SMEM (NSTAGE * STAGE_BYTES)
#define GTHREADS 512

// ---------------- scratch (no allocations allowed) ----------------
__device__ __half g_x[BATCH * 256];
__device__ __half g_h1[BATCH * 1024];
__device__ __half g_h2[BATCH * 1024];
__device__ __half g_a1[BATCH * 512];
__device__ float g_a2[BATCH * 256];
// weights: fp16, transposed to K-major + pre-swizzled blocked tiles
__device__ __half g_w1[256 * 1024];
__device__ __half g_w2[1024 * 1024];
__device__ __half g_hw1[4 * 1024 * 512];
__device__ __half g_hw2[4 * 512 * 256];
__device__ int g_rowmap[BATCH];
__device__ int g_off[5];

// ---------------- helpers (baseline PTX only) ----------------
__device__ __forceinline__ uint32_t smem_u32(const void* p) {
    uint32_t a;
    asm("{ .reg .u64 t; cvta.to.shared.u64 t, %1; cvt.u32.u64 %0, t; }" : "=r"(a) : "l"(p));
    return a;
}
#define LDSM_X4(r0, r1, r2, r3, addr) \
    asm volatile("ldmatrix.sync.aligned.m8n8.x4.shared.b16 {%0,%1,%2,%3}, [%4];" \
                 : "=r"(r0), "=r"(r1), "=r"(r2), "=r"(r3) : "r"(addr))
#define CP16(dst, src) \
    asm volatile("cp.async.cg.shared.global [%0], [%1], 16;" :: "r"(dst), "l"(src) : "memory")
#define CP_COMMIT() asm volatile("cp.async.commit_group;" ::: "memory")
#define CP_WAIT2() asm volatile("cp.async.wait_group 2;" ::: "memory")
#define CP_WAIT0() asm volatile("cp.async.wait_group 0;" ::: "memory")

__device__ __forceinline__ void mma_fp16(float* d, const uint32_t* a, uint32_t b0, uint32_t b1) {
    asm volatile(
        "mma.sync.aligned.m16n8k16.row.col.f32.f16.f16.f32 "
        "{%0,%1,%2,%3}, {%4,%5,%6,%7}, {%8,%9}, {%0,%1,%2,%3};"
        : "+f"(d[0]), "+f"(d[1]), "+f"(d[2]), "+f"(d[3])
        : "r"(a[0]), "r"(a[1]), "r"(a[2]), "r"(a[3]), "r"(b0), "r"(b1));
}
__device__ __forceinline__ uint32_t pack2h(__half a, __half b) {
    return ((uint32_t)__half_as_ushort(b) << 16) | (uint32_t)__half_as_ushort(a);
}
__device__ __forceinline__ uint32_t swz(uint32_t off) { return off ^ ((off >> 3) & 0x70); }

// ---------------- prep: combo partitioning (one block, warp-aggregated) -------
__global__ void partition_k(const int* __restrict__ flags) {
    __shared__ int soff[4];
    const int tid = threadIdx.x;
    const int lane = tid & 31;

    if (tid < 4) soff[tid] = 0;
    __syncthreads();
    for (int i = tid; i < BATCH; i += 1024) {
        int c = flags[2 * i] * 2 + flags[2 * i + 1];
        unsigned same = __match_any_sync(0xFFFFFFFFu, c);
        int leader = __ffs(same) - 1;
        if (lane == leader) atomicAdd(&soff[c], __popc(same));
    }
    __syncthreads();
    if (tid == 0) {
        int o = 0;
        #pragma unroll
        for (int c = 0; c < 4; c++) { int n = soff[c]; g_off[c] = o; soff[c] = o; o += n; }
        g_off[4] = o;
    }
    __syncthreads();
    for (int i = tid; i < BATCH; i += 1024) {
        int c = flags[2 * i] * 2 + flags[2 * i + 1];
        unsigned same = __match_any_sync(0xFFFFFFFFu, c);
        int leader = __ffs(same) - 1;
        int rank = __popc(same & ((1u << lane) - 1u));
        int base = 0;
        if (lane == leader) base = atomicAdd(&soff[c], __popc(same));
        base = __shfl_sync(0xFFFFFFFFu, base, leader);
        g_rowmap[base + rank] = i;
    }
}

// ---------------- prep: convert x to fp16 ----------------
__global__ void splitX_k(const float* __restrict__ x) {
    int idx = blockIdx.x * blockDim.x + threadIdx.x;
    if (idx >= BATCH * 256 / 4) return;
    float4 v = *(const float4*)(x + (size_t)idx * 4);
    *(uint2*)(g_x + (size_t)idx * 4) =
        make_uint2(pack2h(__float2half_rn(v.x), __float2half_rn(v.y)),
                   pack2h(__float2half_rn(v.z), __float2half_rn(v.w)));
}

// ---------------- prep: convert + transpose + swizzle all weights (fp16) ------
// dst blocked layout: [c][nt=N/128][kt=K/64][8192 elems] (tile: n-row 0..127 x k 0..63,
// element (rr,kk) at byte swz(rr*128 + kk*2) within the 16KB tile)
__global__ void splitW_k(const float* __restrict__ W1, const float* __restrict__ W2,
                         const float* __restrict__ HW1, const float* __restrict__ HW2) {
    int z = blockIdx.z;
    int K, N, C;
    const float* src;
    __half* dh;
    if (z == 0)      { K = 256;  N = 1024; C = 1; src = W1;  dh = g_w1; }
    else if (z == 1) { K = 1024; N = 1024; C = 1; src = W2;  dh = g_w2; }
    else if (z == 2) { K = 1024; N = 512;  C = 4; src = HW1; dh = g_hw1; }
    else             { K = 512;  N = 256;  C = 4; src = HW2; dh = g_hw2; }
    const int kg = K >> 3;
    int idx = blockIdx.x * blockDim.x + threadIdx.x;
    if (idx >= C * N * kg) return;
    const int n_ = idx % N;
    const int t  = idx / N;
    const int k8 = (t % kg) * 8;
    const int c  = t / kg;

    const float* s = src + ((size_t)c * K + k8) * N + n_;
    __half hb[8];
    #pragma unroll
    for (int j = 0; j < 8; j++) hb[j] = __float2half_rn(s[(size_t)j * N]);

    const int nt = n_ >> 7, rr = n_ & 127, kt = k8 >> 6, kk = k8 & 63;
    const size_t base = (((size_t)c * (N >> 7) + nt) * (K >> 6) + kt) * 8192;
    const uint32_t sw = swz((uint32_t)rr * 128 + kk * 2);
    *(uint4*)((char*)(dh + base) + sw) = *(uint4*)hb;
}

// ---------------- warp-MMA fp16 GEMM + bias + relu (512 thr, 4x4 warps) -------
// MODE: 0 dense, 1 gather via g_rowmap, 2 compact
// ASRC: 0 g_x, 1 g_h1, 2 g_h2, 3 g_a1
// WSRC: 0 w1, 1 w2, 2 hw1, 3 hw2
// DST : 0 g_h1, 1 g_h2, 2 g_a1, 3 g_a2 fp32
template <int MODE, int ASRC, int WSRC, int DST, int K, int N>
__global__ __launch_bounds__(GTHREADS, 1)
void gemm_mma(const float* __restrict__ Bias)
{
    extern __shared__ __align__(1024) char smem[];
    constexpr int NK = K / KC;
    const int tid = threadIdx.x;
    const int c = blockIdx.z;

    int mstart, mend;
    if (MODE == 0) { mstart = 0; mend = BATCH; }
    else           { mstart = g_off[c]; mend = g_off[c + 1]; }
    const int m0 = mstart + blockIdx.y * 128;
    if (m0 >= mend) return;
    const int n0 = blockIdx.x * 128;

    const float* bc = Bias + (size_t)c * N;
    const uint32_t smb = smem_u32(smem);

    // ---- source pointers ----
    const __half* Ab;
    if (ASRC == 0)      Ab = g_x;
    else if (ASRC == 1) Ab = g_h1;
    else if (ASRC == 2) Ab = g_h2;
    else                Ab = g_a1;
    const __half* Wb;
    if (WSRC == 0)      Wb = g_w1;
    else if (WSRC == 1) Wb = g_w2;
    else if (WSRC == 2) Wb = g_hw1;
    else                Wb = g_hw2;
    const __half* Wt = Wb + (((size_t)c * (N >> 7) + blockIdx.x) * (K >> 6)) * 8192;

    // ---- A loader mapping: 4 threads per row, 32B (16 elems) each ----
    const int ar = tid >> 2;          // 0..127
    const int aq = tid & 3;
    int apos = m0 + ar;
    if (apos > mend - 1) apos = mend - 1;
    const int grow = (MODE == 1) ? g_rowmap[apos] : apos;
    const __half* Ar = Ab + (size_t)grow * K + aq * 16;
    const uint32_t a_sw_base = (uint32_t)ar * 128 + aq * 32;

    auto issue = [&](int kc) {
        const int s = kc % NSTAGE;
        const uint32_t stb = smb + s * STAGE_BYTES;
        const int k0 = kc * KC;
        #pragma unroll
        for (int j = 0; j < 2; j++) {
            uint32_t sw = swz(a_sw_base + j * 16);
            CP16(stb + A_OFF + sw, Ar + k0 + j * 8);
        }
        const __half* wh = Wt + (size_t)kc * 8192 + tid * 16;
        #pragma unroll
        for (int j = 0; j < 2; j++)
            CP16(stb + B_OFF + tid * 32 + j * 16, wh + j * 8);
        CP_COMMIT();
    };

    // ---- warp MMA state: 16 warps in 4x4 grid, warp tile 32x32 ----
    const int wid = tid >> 5;
    const int lane = tid & 31;
    const int wm = (wid & 3) * 32;
    const int wn = (wid >> 2) * 32;

    float acc[2][4][4];   // [m16 frag][n8 frag][quad regs]
    #pragma unroll
    for (int i = 0; i < 2; i++)
        #pragma unroll
        for (int j = 0; j < 4; j++)
            #pragma unroll
            for (int q = 0; q < 4; q++) acc[i][j][q] = 0.0f;

    const int mat = lane >> 3, rin = lane & 7;
    const int a_row = ((mat & 1) << 3) + rin;
    const int a_kh  = (mat >> 1) << 3;
    const int b_row = ((mat >> 1) << 3) + rin;
    const int b_kh  = (mat & 1) << 3;

    auto consume = [&](int s) {
        const uint32_t aSm = smb + s * STAGE_BYTES + A_OFF;
        const uint32_t bSm = smb + s * STAGE_BYTES + B_OFF;
        #pragma unroll
        for (int k16 = 0; k16 < KC / 16; k16++) {
            const int kh = k16 * 16;
            uint32_t ah[2][4], bh[2][4];
            #pragma unroll
            for (int mi = 0; mi < 2; mi++) {
                uint32_t sw = swz((uint32_t)(wm + mi * 16 + a_row) * 128 + (kh + a_kh) * 2);
                LDSM_X4(ah[mi][0], ah[mi][1], ah[mi][2], ah[mi][3], aSm + sw);
            }
            #pragma unroll
            for (int nf = 0; nf < 2; nf++) {
                uint32_t sw = swz((uint32_t)(wn + nf * 16 + b_row) * 128 + (kh + b_kh) * 2);
                LDSM_X4(bh[nf][0], bh[nf][1], bh[nf][2], bh[nf][3], bSm + sw);
            }
            #pragma unroll
            for (int mi = 0; mi < 2; mi++)
                #pragma unroll
                for (int nf = 0; nf < 2; nf++)
                    #pragma unroll
                    for (int nn = 0; nn < 2; nn++)
                        mma_fp16(acc[mi][nf * 2 + nn], ah[mi],
                                 bh[nf][nn * 2], bh[nf][nn * 2 + 1]);
        }
    };

    // ---- 4-stage pipeline ----
    issue(0); issue(1); issue(2);
    for (int kc = 0; kc < NK; kc++) {
        if (kc + 3 < NK) { CP_WAIT2(); } else { CP_WAIT0(); }
        __syncthreads();
        if (kc + 3 < NK) issue(kc + 3);
        consume(kc % NSTAGE);
    }

    // ---- epilogue ----
    __half* Oh = nullptr;
    if (DST == 0)      Oh = g_h1;
    else if (DST == 1) Oh = g_h2;
    else if (DST == 2) Oh = g_a1;

    const int qrow = lane >> 2;
    const int qcol = (lane & 3) * 2;
    #pragma unroll
    for (int mi = 0; mi < 2; mi++) {
        #pragma unroll
        for (int half = 0; half < 2; half++) {
            const int m = m0 + wm + mi * 16 + qrow + half * 8;
            if (MODE != 0 && m >= mend) continue;
            #pragma unroll
            for (int nj = 0; nj < 4; nj++) {
                const int col = n0 + wn + nj * 8 + qcol;
                float v0 = acc[mi][nj][half * 2 + 0] + __ldg(bc + col);
                float v1 = acc[mi][nj][half * 2 + 1] + __ldg(bc + col + 1);
                v0 = fmaxf(v0, 0.0f); v1 = fmaxf(v1, 0.0f);
                if (DST == 3) {
                    *(float2*)(g_a2 + (size_t)m * N + col) = make_float2(v0, v1);
                } else {
                    *(uint32_t*)(Oh + (size_t)m * N + col) =
                        pack2h(__float2half_rn(v0), __float2half_rn(v1));
                }
            }
        }
    }
}

// ---------------- final head (dot 256 + bias + sigmoid + scatter) ----------------
__global__ void head3_k(const float* __restrict__ HW3,
                        const float* __restrict__ Hb3,
                        float* __restrict__ out)
{
    int gwarp = (blockIdx.x * blockDim.x + threadIdx.x) >> 5;
    int lane = threadIdx.x & 31;
    if (gwarp >= BATCH) return;

    int c;
    if (gwarp < g_off[1]) c = 0;
    else if (gwarp < g_off[2]) c = 1;
    else if (gwarp < g_off[3]) c = 2;
    else c = 3;

    const float* a = g_a2 + (size_t)gwarp * 256;
    const float* w = HW3 + (size_t)c * 256;

    float s = 0.0f;
    #pragma unroll
    for (int j = lane; j < 256; j += 32) s = fmaf(a[j], w[j], s);
    #pragma unroll
    for (int o = 16; o; o >>= 1) s += __shfl_xor_sync(0xFFFFFFFFu, s, o);

    if (lane == 0) {
        s += Hb3[c];
        out[g_rowmap[gwarp]] = 1.0f / (1.0f + expf(-s));
    }
}

// ---------------- launch ----------------
extern "C" void kernel_launch(void* const* d_in, const int* in_sizes, int n_in,
                              void* d_out, int out_size)
{
    const float* x     = (const float*)d_in[0];
    const int*   flags = (const int*)  d_in[1];
    const float* W1    = (const float*)d_in[2];
    const float* b1    = (const float*)d_in[3];
    const float* W2    = (const float*)d_in[4];
    const float* b2    = (const float*)d_in[5];
    const float* HW1   = (const float*)d_in[6];
    const float* Hb1   = (const float*)d_in[7];
    const float* HW2   = (const float*)d_in[8];
    const float* Hb2   = (const float*)d_in[9];
    const float* HW3   = (const float*)d_in[10];
    const float* Hb3   = (const float*)d_in[11];
    float* out = (float*)d_out;

    cudaFuncSetAttribute(gemm_mma<0, 0, 0, 0, 256, 1024>,
                         cudaFuncAttributeMaxDynamicSharedMemorySize, GEMM_SMEM);
    cudaFuncSetAttribute(gemm_mma<0, 1, 1, 1, 1024, 1024>,
                         cudaFuncAttributeMaxDynamicSharedMemorySize, GEMM_SMEM);
    cudaFuncSetAttribute(gemm_mma<1, 2, 2, 2, 1024, 512>,
                         cudaFuncAttributeMaxDynamicSharedMemorySize, GEMM_SMEM);
    cudaFuncSetAttribute(gemm_mma<2, 3, 3, 3, 512, 256>,
                         cudaFuncAttributeMaxDynamicSharedMemorySize, GEMM_SMEM);

    // prep
    partition_k<<<1, 1024>>>(flags);
    splitX_k<<<BATCH * 256 / 4 / 256, 256>>>(x);
    splitW_k<<<dim3(1024, 1, 4), 256>>>(W1, W2, HW1, HW2);

    // trunk L1: [16384,256] @ [256,1024] -> h1
    gemm_mma<0, 0, 0, 0, 256, 1024><<<dim3(8, 128, 1), GTHREADS, GEMM_SMEM>>>(b1);
    // trunk L2: [16384,1024] @ [1024,1024] -> h2
    gemm_mma<0, 1, 1, 1, 1024, 1024><<<dim3(8, 128, 1), GTHREADS, GEMM_SMEM>>>(b2);
    // head L1 (gather per-combo): [cnt_c,1024] @ HW1[c][1024,512] -> a1
    gemm_mma<1, 2, 2, 2, 1024, 512><<<dim3(4, 128, 4), GTHREADS, GEMM_SMEM>>>(Hb1);
    // head L2 (compact per-combo): [cnt_c,512] @ HW2[c][512,256] -> a2 fp32
    gemm_mma<2, 3, 3, 3, 512, 256><<<dim3(2, 128, 4), GTHREADS, GEMM_SMEM>>>(Hb2);

    head3_k<<<(BATCH * 32) / 256, 256>>>(HW3, Hb3, out);
}

// round 11
// speedup vs baseline: 2.4898x; 1.0129x over previous
#include <cuda_runtime.h>
#include <cuda_fp16.h>
#include <math.h>
#include <stdint.h>

#define BATCH 16384
#define KC 64                       // K elements per SMEM stage
#define STAGE_BYTES 49152           // A 16KB + B 32KB
#define A_OFF 0
#define B_OFF 16384
#define NSTAGE 4
#define GEMM_SMEM (NSTAGE * STAGE_BYTES)
#define GTHREADS 512

// ---------------- scratch (no allocations allowed) ----------------
__device__ __half g_x[BATCH * 256];
__device__ __half g_h1[BATCH * 1024];
__device__ __half g_h2[BATCH * 1024];
__device__ __half g_a1[BATCH * 512];
__device__ float g_a2[BATCH * 256];
// weights: fp16, transposed to K-major + pre-swizzled blocked tiles
// blocked layout: [c][nt=N/256][kt=K/64][16384 elems] (tile: n-row 0..255 x k 0..63,
// element (rr,kk) at byte swz(rr*128 + kk*2) within the 32KB tile)
__device__ __half g_w1[256 * 1024];
__device__ __half g_w2[1024 * 1024];
__device__ __half g_hw1[4 * 1024 * 512];
__device__ __half g_hw2[4 * 512 * 256];
__device__ int g_rowmap[BATCH];
__device__ int g_off[5];

// ---------------- helpers (baseline PTX only) ----------------
__device__ __forceinline__ uint32_t smem_u32(const void* p) {
    uint32_t a;
    asm("{ .reg .u64 t; cvta.to.shared.u64 t, %1; cvt.u32.u64 %0, t; }" : "=r"(a) : "l"(p));
    return a;
}
#define LDSM_X4(r0, r1, r2, r3, addr) \
    asm volatile("ldmatrix.sync.aligned.m8n8.x4.shared.b16 {%0,%1,%2,%3}, [%4];" \
                 : "=r"(r0), "=r"(r1), "=r"(r2), "=r"(r3) : "r"(addr))
#define CP16(dst, src) \
    asm volatile("cp.async.cg.shared.global [%0], [%1], 16;" :: "r"(dst), "l"(src) : "memory")
#define CP_COMMIT() asm volatile("cp.async.commit_group;" ::: "memory")
#define CP_WAIT2() asm volatile("cp.async.wait_group 2;" ::: "memory")
#define CP_WAIT0() asm volatile("cp.async.wait_group 0;" ::: "memory")

__device__ __forceinline__ void mma_fp16(float* d, const uint32_t* a, uint32_t b0, uint32_t b1) {
    asm volatile(
        "mma.sync.aligned.m16n8k16.row.col.f32.f16.f16.f32 "
        "{%0,%1,%2,%3}, {%4,%5,%6,%7}, {%8,%9}, {%0,%1,%2,%3};"
        : "+f"(d[0]), "+f"(d[1]), "+f"(d[2]), "+f"(d[3])
        : "r"(a[0]), "r"(a[1]), "r"(a[2]), "r"(a[3]), "r"(b0), "r"(b1));
}
__device__ __forceinline__ uint32_t pack2h(__half a, __half b) {
    return ((uint32_t)__half_as_ushort(b) << 16) | (uint32_t)__half_as_ushort(a);
}
__device__ __forceinline__ uint32_t swz(uint32_t off) { return off ^ ((off >> 3) & 0x70); }

// ---------------- prep: combo partitioning (one block, warp-aggregated) -------
__global__ void partition_k(const int* __restrict__ flags) {
    __shared__ int soff[4];
    const int tid = threadIdx.x;
    const int lane = tid & 31;

    if (tid < 4) soff[tid] = 0;
    __syncthreads();
    for (int i = tid; i < BATCH; i += 1024) {
        int c = flags[2 * i] * 2 + flags[2 * i + 1];
        unsigned same = __match_any_sync(0xFFFFFFFFu, c);
        int leader = __ffs(same) - 1;
        if (lane == leader) atomicAdd(&soff[c], __popc(same));
    }
    __syncthreads();
    if (tid == 0) {
        int o = 0;
        #pragma unroll
        for (int c = 0; c < 4; c++) { int n = soff[c]; g_off[c] = o; soff[c] = o; o += n; }
        g_off[4] = o;
    }
    __syncthreads();
    for (int i = tid; i < BATCH; i += 1024) {
        int c = flags[2 * i] * 2 + flags[2 * i + 1];
        unsigned same = __match_any_sync(0xFFFFFFFFu, c);
        int leader = __ffs(same) - 1;
        int rank = __popc(same & ((1u << lane) - 1u));
        int base = 0;
        if (lane == leader) base = atomicAdd(&soff[c], __popc(same));
        base = __shfl_sync(0xFFFFFFFFu, base, leader);
        g_rowmap[base + rank] = i;
    }
}

// ---------------- prep: convert x to fp16 ----------------
__global__ void splitX_k(const float* __restrict__ x) {
    int idx = blockIdx.x * blockDim.x + threadIdx.x;
    if (idx >= BATCH * 256 / 4) return;
    float4 v = *(const float4*)(x + (size_t)idx * 4);
    *(uint2*)(g_x + (size_t)idx * 4) =
        make_uint2(pack2h(__float2half_rn(v.x), __float2half_rn(v.y)),
                   pack2h(__float2half_rn(v.z), __float2half_rn(v.w)));
}

// ---------------- prep: convert + transpose + swizzle all weights (fp16) ------
__global__ void splitW_k(const float* __restrict__ W1, const float* __restrict__ W2,
                         const float* __restrict__ HW1, const float* __restrict__ HW2) {
    int z = blockIdx.z;
    int K, N, C;
    const float* src;
    __half* dh;
    if (z == 0)      { K = 256;  N = 1024; C = 1; src = W1;  dh = g_w1; }
    else if (z == 1) { K = 1024; N = 1024; C = 1; src = W2;  dh = g_w2; }
    else if (z == 2) { K = 1024; N = 512;  C = 4; src = HW1; dh = g_hw1; }
    else             { K = 512;  N = 256;  C = 4; src = HW2; dh = g_hw2; }
    const int kg = K >> 3;
    int idx = blockIdx.x * blockDim.x + threadIdx.x;
    if (idx >= C * N * kg) return;
    const int n_ = idx % N;
    const int t  = idx / N;
    const int k8 = (t % kg) * 8;
    const int c  = t / kg;

    const float* s = src + ((size_t)c * K + k8) * N + n_;
    __half hb[8];
    #pragma unroll
    for (int j = 0; j < 8; j++) hb[j] = __float2half_rn(s[(size_t)j * N]);

    const int nt = n_ >> 8, rr = n_ & 255, kt = k8 >> 6, kk = k8 & 63;
    const size_t base = (((size_t)c * (N >> 8) + nt) * (K >> 6) + kt) * 16384;
    const uint32_t sw = swz((uint32_t)rr * 128 + kk * 2);
    *(uint4*)((char*)(dh + base) + sw) = *(uint4*)hb;
}

// ---------------- warp-MMA fp16 GEMM + bias + relu (CTA 128x256, warp 32x64) --
// MODE: 0 dense, 1 gather via g_rowmap, 2 compact
// ASRC: 0 g_x, 1 g_h1, 2 g_h2, 3 g_a1
// WSRC: 0 w1, 1 w2, 2 hw1, 3 hw2
// DST : 0 g_h1, 1 g_h2, 2 g_a1, 3 g_a2 fp32
template <int MODE, int ASRC, int WSRC, int DST, int K, int N>
__global__ __launch_bounds__(GTHREADS, 1)
void gemm_mma(const float* __restrict__ Bias)
{
    extern __shared__ __align__(1024) char smem[];
    constexpr int NK = K / KC;
    const int tid = threadIdx.x;
    const int c = blockIdx.z;

    int mstart, mend;
    if (MODE == 0) { mstart = 0; mend = BATCH; }
    else           { mstart = g_off[c]; mend = g_off[c + 1]; }
    const int m0 = mstart + blockIdx.y * 128;
    if (m0 >= mend) return;
    const int n0 = blockIdx.x * 256;

    const float* bc = Bias + (size_t)c * N;
    const uint32_t smb = smem_u32(smem);

    // ---- source pointers ----
    const __half* Ab;
    if (ASRC == 0)      Ab = g_x;
    else if (ASRC == 1) Ab = g_h1;
    else if (ASRC == 2) Ab = g_h2;
    else                Ab = g_a1;
    const __half* Wb;
    if (WSRC == 0)      Wb = g_w1;
    else if (WSRC == 1) Wb = g_w2;
    else if (WSRC == 2) Wb = g_hw1;
    else                Wb = g_hw2;
    const __half* Wt = Wb + (((size_t)c * (N >> 8) + blockIdx.x) * (K >> 6)) * 16384;

    // ---- A loader mapping: 4 threads per row, 32B (16 elems) each ----
    const int ar = tid >> 2;          // 0..127
    const int aq = tid & 3;
    int apos = m0 + ar;
    if (apos > mend - 1) apos = mend - 1;
    const int grow = (MODE == 1) ? g_rowmap[apos] : apos;
    const __half* Ar = Ab + (size_t)grow * K + aq * 16;
    const uint32_t a_sw_base = (uint32_t)ar * 128 + aq * 32;

    auto issue = [&](int kc) {
        const int s = kc % NSTAGE;
        const uint32_t stb = smb + s * STAGE_BYTES;
        const int k0 = kc * KC;
        #pragma unroll
        for (int j = 0; j < 2; j++) {
            uint32_t sw = swz(a_sw_base + j * 16);
            CP16(stb + A_OFF + sw, Ar + k0 + j * 8);
        }
        const __half* wh = Wt + (size_t)kc * 16384 + tid * 32;
        #pragma unroll
        for (int j = 0; j < 4; j++)
            CP16(stb + B_OFF + tid * 64 + j * 16, wh + j * 8);
        CP_COMMIT();
    };

    // ---- warp MMA state: 16 warps in 4(m) x 4(n) grid, warp tile 32x64 ----
    const int wid = tid >> 5;
    const int lane = tid & 31;
    const int wm = (wid & 3) * 32;
    const int wn = (wid >> 2) * 64;

    float acc[2][8][4];   // [m16 frag][n8 frag][quad regs]
    #pragma unroll
    for (int i = 0; i < 2; i++)
        #pragma unroll
        for (int j = 0; j < 8; j++)
            #pragma unroll
            for (int q = 0; q < 4; q++) acc[i][j][q] = 0.0f;

    const int mat = lane >> 3, rin = lane & 7;
    const int a_row = ((mat & 1) << 3) + rin;
    const int a_kh  = (mat >> 1) << 3;
    const int b_row = ((mat >> 1) << 3) + rin;
    const int b_kh  = (mat & 1) << 3;

    auto consume = [&](int s) {
        const uint32_t aSm = smb + s * STAGE_BYTES + A_OFF;
        const uint32_t bSm = smb + s * STAGE_BYTES + B_OFF;
        #pragma unroll
        for (int k16 = 0; k16 < KC / 16; k16++) {
            const int kh = k16 * 16;
            uint32_t ah[2][4], bh[4][4];
            #pragma unroll
            for (int mi = 0; mi < 2; mi++) {
                uint32_t sw = swz((uint32_t)(wm + mi * 16 + a_row) * 128 + (kh + a_kh) * 2);
                LDSM_X4(ah[mi][0], ah[mi][1], ah[mi][2], ah[mi][3], aSm + sw);
            }
            #pragma unroll
            for (int nf = 0; nf < 4; nf++) {
                uint32_t sw = swz((uint32_t)(wn + nf * 16 + b_row) * 128 + (kh + b_kh) * 2);
                LDSM_X4(bh[nf][0], bh[nf][1], bh[nf][2], bh[nf][3], bSm + sw);
            }
            #pragma unroll
            for (int mi = 0; mi < 2; mi++)
                #pragma unroll
                for (int nf = 0; nf < 4; nf++)
                    #pragma unroll
                    for (int nn = 0; nn < 2; nn++)
                        mma_fp16(acc[mi][nf * 2 + nn], ah[mi],
                                 bh[nf][nn * 2], bh[nf][nn * 2 + 1]);
        }
    };

    // ---- 4-stage pipeline ----
    issue(0); issue(1); issue(2);
    for (int kc = 0; kc < NK; kc++) {
        if (kc + 3 < NK) { CP_WAIT2(); } else { CP_WAIT0(); }
        __syncthreads();
        if (kc + 3 < NK) issue(kc + 3);
        consume(kc % NSTAGE);
    }

    // ---- epilogue ----
    __half* Oh = nullptr;
    if (DST == 0)      Oh = g_h1;
    else if (DST == 1) Oh = g_h2;
    else if (DST == 2) Oh = g_a1;

    const int qrow = lane >> 2;
    const int qcol = (lane & 3) * 2;
    #pragma unroll
    for (int mi = 0; mi < 2; mi++) {
        #pragma unroll
        for (int half = 0; half < 2; half++) {
            const int m = m0 + wm + mi * 16 + qrow + half * 8;
            if (MODE != 0 && m >= mend) continue;
            #pragma unroll
            for (int nj = 0; nj < 8; nj++) {
                const int col = n0 + wn + nj * 8 + qcol;
                float v0 = acc[mi][nj][half * 2 + 0] + __ldg(bc + col);
                float v1 = acc[mi][nj][half * 2 + 1] + __ldg(bc + col + 1);
                v0 = fmaxf(v0, 0.0f); v1 = fmaxf(v1, 0.0f);
                if (DST == 3) {
                    *(float2*)(g_a2 + (size_t)m * N + col) = make_float2(v0, v1);
                } else {
                    *(uint32_t*)(Oh + (size_t)m * N + col) =
                        pack2h(__float2half_rn(v0), __float2half_rn(v1));
                }
            }
        }
    }
}

// ---------------- final head (dot 256 + bias + sigmoid + scatter) ----------------
__global__ void head3_k(const float* __restrict__ HW3,
                        const float* __restrict__ Hb3,
                        float* __restrict__ out)
{
    int gwarp = (blockIdx.x * blockDim.x + threadIdx.x) >> 5;
    int lane = threadIdx.x & 31;
    if (gwarp >= BATCH) return;

    int c;
    if (gwarp < g_off[1]) c = 0;
    else if (gwarp < g_off[2]) c = 1;
    else if (gwarp < g_off[3]) c = 2;
    else c = 3;

    const float* a = g_a2 + (size_t)gwarp * 256;
    const float* w = HW3 + (size_t)c * 256;

    float s = 0.0f;
    #pragma unroll
    for (int j = lane; j < 256; j += 32) s = fmaf(a[j], w[j], s);
    #pragma unroll
    for (int o = 16; o; o >>= 1) s += __shfl_xor_sync(0xFFFFFFFFu, s, o);

    if (lane == 0) {
        s += Hb3[c];
        out[g_rowmap[gwarp]] = 1.0f / (1.0f + expf(-s));
    }
}

// ---------------- launch ----------------
extern "C" void kernel_launch(void* const* d_in, const int* in_sizes, int n_in,
                              void* d_out, int out_size)
{
    const float* x     = (const float*)d_in[0];
    const int*   flags = (const int*)  d_in[1];
    const float* W1    = (const float*)d_in[2];
    const float* b1    = (const float*)d_in[3];
    const float* W2    = (const float*)d_in[4];
    const float* b2    = (const float*)d_in[5];
    const float* HW1   = (const float*)d_in[6];
    const float* Hb1   = (const float*)d_in[7];
    const float* HW2   = (const float*)d_in[8];
    const float* Hb2   = (const float*)d_in[9];
    const float* HW3   = (const float*)d_in[10];
    const float* Hb3   = (const float*)d_in[11];
    float* out = (float*)d_out;

    cudaFuncSetAttribute(gemm_mma<0, 0, 0, 0, 256, 1024>,
                         cudaFuncAttributeMaxDynamicSharedMemorySize, GEMM_SMEM);
    cudaFuncSetAttribute(gemm_mma<0, 1, 1, 1, 1024, 1024>,
                         cudaFuncAttributeMaxDynamicSharedMemorySize, GEMM_SMEM);
    cudaFuncSetAttribute(gemm_mma<1, 2, 2, 2, 1024, 512>,
                         cudaFuncAttributeMaxDynamicSharedMemorySize, GEMM_SMEM);
    cudaFuncSetAttribute(gemm_mma<2, 3, 3, 3, 512, 256>,
                         cudaFuncAttributeMaxDynamicSharedMemorySize, GEMM_SMEM);

    // prep
    partition_k<<<1, 1024>>>(flags);
    splitX_k<<<BATCH * 256 / 4 / 256, 256>>>(x);
    splitW_k<<<dim3(1024, 1, 4), 256>>>(W1, W2, HW1, HW2);

    // trunk L1: [16384,256] @ [256,1024] -> h1
    gemm_mma<0, 0, 0, 0, 256, 1024><<<dim3(4, 128, 1), GTHREADS, GEMM_SMEM>>>(b1);
    // trunk L2: [16384,1024] @ [1024,1024] -> h2
    gemm_mma<0, 1, 1, 1, 1024, 1024><<<dim3(4, 128, 1), GTHREADS, GEMM_SMEM>>>(b2);
    // head L1 (gather per-combo): [cnt_c,1024] @ HW1[c][1024,512] -> a1
    gemm_mma<1, 2, 2, 2, 1024, 512><<<dim3(2, 128, 4), GTHREADS, GEMM_SMEM>>>(Hb1);
    // head L2 (compact per-combo): [cnt_c,512] @ HW2[c][512,256] -> a2 fp32
    gemm_mma<2, 3, 3, 3, 512, 256><<<dim3(1, 128, 4), GTHREADS, GEMM_SMEM>>>(Hb2);

    head3_k<<<(BATCH * 32) / 256, 256>>>(HW3, Hb3, out);
}

// round 12
// speedup vs baseline: 2.5243x; 1.0138x over previous
#include <cuda_runtime.h>
#include <cuda_fp16.h>
#include <math.h>
#include <stdint.h>

#define BATCH 16384
#define KC 64                       // K elements per SMEM stage
#define STAGE_BYTES 32768           // A 16KB + B 16KB
#define A_OFF 0
#define B_OFF 16384
#define NSTAGE 3
#define GEMM_SMEM (NSTAGE * STAGE_BYTES)
#define GTHREADS 256

// ---------------- scratch (no allocations allowed) ----------------
__device__ __half g_x[BATCH * 256];
__device__ __half g_h1[BATCH * 1024];
__device__ __half g_h2[BATCH * 1024];
__device__ __half g_a1[BATCH * 512];
__device__ float g_a2[BATCH * 256];
// weights: fp16, transposed to K-major + pre-swizzled blocked tiles
// blocked layout: [c][nt=N/128][kt=K/64][8192 elems] (tile: n-row 0..127 x k 0..63,
// element (rr,kk) at byte swz(rr*128 + kk*2) within the 16KB tile)
__device__ __half g_w1[256 * 1024];
__device__ __half g_w2[1024 * 1024];
__device__ __half g_hw1[4 * 1024 * 512];
__device__ __half g_hw2[4 * 512 * 256];
__device__ int g_rowmap[BATCH];
__device__ int g_off[5];

// ---------------- helpers (baseline PTX only) ----------------
__device__ __forceinline__ uint32_t smem_u32(const void* p) {
    uint32_t a;
    asm("{ .reg .u64 t; cvta.to.shared.u64 t, %1; cvt.u32.u64 %0, t; }" : "=r"(a) : "l"(p));
    return a;
}
#define LDSM_X4(r0, r1, r2, r3, addr) \
    asm volatile("ldmatrix.sync.aligned.m8n8.x4.shared.b16 {%0,%1,%2,%3}, [%4];" \
                 : "=r"(r0), "=r"(r1), "=r"(r2), "=r"(r3) : "r"(addr))
#define CP16(dst, src) \
    asm volatile("cp.async.cg.shared.global [%0], [%1], 16;" :: "r"(dst), "l"(src) : "memory")
#define CP_COMMIT() asm volatile("cp.async.commit_group;" ::: "memory")
#define CP_WAIT1() asm volatile("cp.async.wait_group 1;" ::: "memory")
#define CP_WAIT0() asm volatile("cp.async.wait_group 0;" ::: "memory")

__device__ __forceinline__ void mma_fp16(float* d, const uint32_t* a, uint32_t b0, uint32_t b1) {
    asm volatile(
        "mma.sync.aligned.m16n8k16.row.col.f32.f16.f16.f32 "
        "{%0,%1,%2,%3}, {%4,%5,%6,%7}, {%8,%9}, {%0,%1,%2,%3};"
        : "+f"(d[0]), "+f"(d[1]), "+f"(d[2]), "+f"(d[3])
        : "r"(a[0]), "r"(a[1]), "r"(a[2]), "r"(a[3]), "r"(b0), "r"(b1));
}
__device__ __forceinline__ uint32_t pack2h(__half a, __half b) {
    return ((uint32_t)__half_as_ushort(b) << 16) | (uint32_t)__half_as_ushort(a);
}
__device__ __forceinline__ uint32_t swz(uint32_t off) { return off ^ ((off >> 3) & 0x70); }

// ---------------- prep: combo partitioning (one block, warp-aggregated) -------
__global__ void partition_k(const int* __restrict__ flags) {
    __shared__ int soff[4];
    const int tid = threadIdx.x;
    const int lane = tid & 31;

    if (tid < 4) soff[tid] = 0;
    __syncthreads();
    for (int i = tid; i < BATCH; i += 1024) {
        int c = flags[2 * i] * 2 + flags[2 * i + 1];
        unsigned same = __match_any_sync(0xFFFFFFFFu, c);
        int leader = __ffs(same) - 1;
        if (lane == leader) atomicAdd(&soff[c], __popc(same));
    }
    __syncthreads();
    if (tid == 0) {
        int o = 0;
        #pragma unroll
        for (int c = 0; c < 4; c++) { int n = soff[c]; g_off[c] = o; soff[c] = o; o += n; }
        g_off[4] = o;
    }
    __syncthreads();
    for (int i = tid; i < BATCH; i += 1024) {
        int c = flags[2 * i] * 2 + flags[2 * i + 1];
        unsigned same = __match_any_sync(0xFFFFFFFFu, c);
        int leader = __ffs(same) - 1;
        int rank = __popc(same & ((1u << lane) - 1u));
        int base = 0;
        if (lane == leader) base = atomicAdd(&soff[c], __popc(same));
        base = __shfl_sync(0xFFFFFFFFu, base, leader);
        g_rowmap[base + rank] = i;
    }
}

// ---------------- prep: convert x to fp16 ----------------
__global__ void splitX_k(const float* __restrict__ x) {
    int idx = blockIdx.x * blockDim.x + threadIdx.x;
    if (idx >= BATCH * 256 / 4) return;
    float4 v = *(const float4*)(x + (size_t)idx * 4);
    *(uint2*)(g_x + (size_t)idx * 4) =
        make_uint2(pack2h(__float2half_rn(v.x), __float2half_rn(v.y)),
                   pack2h(__float2half_rn(v.z), __float2half_rn(v.w)));
}

// ---------------- prep: convert + transpose + swizzle all weights (fp16) ------
__global__ void splitW_k(const float* __restrict__ W1, const float* __restrict__ W2,
                         const float* __restrict__ HW1, const float* __restrict__ HW2) {
    int z = blockIdx.z;
    int K, N, C;
    const float* src;
    __half* dh;
    if (z == 0)      { K = 256;  N = 1024; C = 1; src = W1;  dh = g_w1; }
    else if (z == 1) { K = 1024; N = 1024; C = 1; src = W2;  dh = g_w2; }
    else if (z == 2) { K = 1024; N = 512;  C = 4; src = HW1; dh = g_hw1; }
    else             { K = 512;  N = 256;  C = 4; src = HW2; dh = g_hw2; }
    const int kg = K >> 3;
    int idx = blockIdx.x * blockDim.x + threadIdx.x;
    if (idx >= C * N * kg) return;
    const int n_ = idx % N;
    const int t  = idx / N;
    const int k8 = (t % kg) * 8;
    const int c  = t / kg;

    const float* s = src + ((size_t)c * K + k8) * N + n_;
    __half hb[8];
    #pragma unroll
    for (int j = 0; j < 8; j++) hb[j] = __float2half_rn(s[(size_t)j * N]);

    const int nt = n_ >> 7, rr = n_ & 127, kt = k8 >> 6, kk = k8 & 63;
    const size_t base = (((size_t)c * (N >> 7) + nt) * (K >> 6) + kt) * 8192;
    const uint32_t sw = swz((uint32_t)rr * 128 + kk * 2);
    *(uint4*)((char*)(dh + base) + sw) = *(uint4*)hb;
}

// ---------------- warp-MMA fp16 GEMM + bias + relu (256 thr, 2 CTA/SM) --------
// CTA tile 128x128, 8 warps in 4(m) x 2(n) grid, warp tile 32x64.
// MODE: 0 dense, 1 gather via g_rowmap, 2 compact
// ASRC: 0 g_x, 1 g_h1, 2 g_h2, 3 g_a1
// WSRC: 0 w1, 1 w2, 2 hw1, 3 hw2
// DST : 0 g_h1, 1 g_h2, 2 g_a1, 3 g_a2 fp32
template <int MODE, int ASRC, int WSRC, int DST, int K, int N>
__global__ __launch_bounds__(GTHREADS, 2)
void gemm_mma(const float* __restrict__ Bias)
{
    extern __shared__ __align__(1024) char smem[];
    constexpr int NK = K / KC;
    const int tid = threadIdx.x;
    const int c = blockIdx.z;

    int mstart, mend;
    if (MODE == 0) { mstart = 0; mend = BATCH; }
    else           { mstart = g_off[c]; mend = g_off[c + 1]; }
    const int m0 = mstart + blockIdx.y * 128;
    if (m0 >= mend) return;
    const int n0 = blockIdx.x * 128;

    const float* bc = Bias + (size_t)c * N;
    const uint32_t smb = smem_u32(smem);

    // ---- source pointers ----
    const __half* Ab;
    if (ASRC == 0)      Ab = g_x;
    else if (ASRC == 1) Ab = g_h1;
    else if (ASRC == 2) Ab = g_h2;
    else                Ab = g_a1;
    const __half* Wb;
    if (WSRC == 0)      Wb = g_w1;
    else if (WSRC == 1) Wb = g_w2;
    else if (WSRC == 2) Wb = g_hw1;
    else                Wb = g_hw2;
    const __half* Wt = Wb + (((size_t)c * (N >> 7) + blockIdx.x) * (K >> 6)) * 8192;

    // ---- A loader mapping: 2 threads per row, 64B (32 elems) each ----
    const int ar = tid >> 1;          // 0..127
    const int aqe = (tid & 1) * 32;   // elem offset within row
    int apos = m0 + ar;
    if (apos > mend - 1) apos = mend - 1;
    const int grow = (MODE == 1) ? g_rowmap[apos] : apos;
    const __half* Ar = Ab + (size_t)grow * K + aqe;
    const uint32_t a_sw_base = (uint32_t)ar * 128 + aqe * 2;

    auto issue = [&](int kc) {
        const int s = kc % NSTAGE;
        const uint32_t stb = smb + s * STAGE_BYTES;
        const int k0 = kc * KC;
        #pragma unroll
        for (int j = 0; j < 4; j++) {
            uint32_t sw = swz(a_sw_base + j * 16);
            CP16(stb + A_OFF + sw, Ar + k0 + j * 8);
        }
        const __half* wh = Wt + (size_t)kc * 8192 + tid * 32;
        #pragma unroll
        for (int j = 0; j < 4; j++)
            CP16(stb + B_OFF + tid * 64 + j * 16, wh + j * 8);
        CP_COMMIT();
    };

    // ---- warp MMA state: 8 warps in 4(m) x 2(n) grid, warp tile 32x64 ----
    const int wid = tid >> 5;
    const int lane = tid & 31;
    const int wm = (wid & 3) * 32;
    const int wn = (wid >> 2) * 64;

    float acc[2][8][4];   // [m16 frag][n8 frag][quad regs]
    #pragma unroll
    for (int i = 0; i < 2; i++)
        #pragma unroll
        for (int j = 0; j < 8; j++)
            #pragma unroll
            for (int q = 0; q < 4; q++) acc[i][j][q] = 0.0f;

    const int mat = lane >> 3, rin = lane & 7;
    const int a_row = ((mat & 1) << 3) + rin;
    const int a_kh  = (mat >> 1) << 3;
    const int b_row = ((mat >> 1) << 3) + rin;
    const int b_kh  = (mat & 1) << 3;

    auto consume = [&](int s) {
        const uint32_t aSm = smb + s * STAGE_BYTES + A_OFF;
        const uint32_t bSm = smb + s * STAGE_BYTES + B_OFF;
        #pragma unroll
        for (int k16 = 0; k16 < KC / 16; k16++) {
            const int kh = k16 * 16;
            uint32_t ah[2][4], bh[4][4];
            #pragma unroll
            for (int mi = 0; mi < 2; mi++) {
                uint32_t sw = swz((uint32_t)(wm + mi * 16 + a_row) * 128 + (kh + a_kh) * 2);
                LDSM_X4(ah[mi][0], ah[mi][1], ah[mi][2], ah[mi][3], aSm + sw);
            }
            #pragma unroll
            for (int nf = 0; nf < 4; nf++) {
                uint32_t sw = swz((uint32_t)(wn + nf * 16 + b_row) * 128 + (kh + b_kh) * 2);
                LDSM_X4(bh[nf][0], bh[nf][1], bh[nf][2], bh[nf][3], bSm + sw);
            }
            #pragma unroll
            for (int mi = 0; mi < 2; mi++)
                #pragma unroll
                for (int nf = 0; nf < 4; nf++)
                    #pragma unroll
                    for (int nn = 0; nn < 2; nn++)
                        mma_fp16(acc[mi][nf * 2 + nn], ah[mi],
                                 bh[nf][nn * 2], bh[nf][nn * 2 + 1]);
        }
    };

    // ---- 3-stage pipeline ----
    issue(0); issue(1);
    for (int kc = 0; kc < NK; kc++) {
        if (kc + 2 < NK) { CP_WAIT1(); } else { CP_WAIT0(); }
        __syncthreads();
        if (kc + 2 < NK) issue(kc + 2);
        consume(kc % NSTAGE);
    }

    // ---- epilogue ----
    __half* Oh = nullptr;
    if (DST == 0)      Oh = g_h1;
    else if (DST == 1) Oh = g_h2;
    else if (DST == 2) Oh = g_a1;

    const int qrow = lane >> 2;
    const int qcol = (lane & 3) * 2;
    #pragma unroll
    for (int mi = 0; mi < 2; mi++) {
        #pragma unroll
        for (int half = 0; half < 2; half++) {
            const int m = m0 + wm + mi * 16 + qrow + half * 8;
            if (MODE != 0 && m >= mend) continue;
            #pragma unroll
            for (int nj = 0; nj < 8; nj++) {
                const int col = n0 + wn + nj * 8 + qcol;
                float v0 = acc[mi][nj][half * 2 + 0] + __ldg(bc + col);
                float v1 = acc[mi][nj][half * 2 + 1] + __ldg(bc + col + 1);
                v0 = fmaxf(v0, 0.0f); v1 = fmaxf(v1, 0.0f);
                if (DST == 3) {
                    *(float2*)(g_a2 + (size_t)m * N + col) = make_float2(v0, v1);
                } else {
                    *(uint32_t*)(Oh + (size_t)m * N + col) =
                        pack2h(__float2half_rn(v0), __float2half_rn(v1));
                }
            }
        }
    }
}

// ---------------- final head (dot 256 + bias + sigmoid + scatter) ----------------
__global__ void head3_k(const float* __restrict__ HW3,
                        const float* __restrict__ Hb3,
                        float* __restrict__ out)
{
    int gwarp = (blockIdx.x * blockDim.x + threadIdx.x) >> 5;
    int lane = threadIdx.x & 31;
    if (gwarp >= BATCH) return;

    int c;
    if (gwarp < g_off[1]) c = 0;
    else if (gwarp < g_off[2]) c = 1;
    else if (gwarp < g_off[3]) c = 2;
    else c = 3;

    const float* a = g_a2 + (size_t)gwarp * 256;
    const float* w = HW3 + (size_t)c * 256;

    float s = 0.0f;
    #pragma unroll
    for (int j = lane; j < 256; j += 32) s = fmaf(a[j], w[j], s);
    #pragma unroll
    for (int o = 16; o; o >>= 1) s += __shfl_xor_sync(0xFFFFFFFFu, s, o);

    if (lane == 0) {
        s += Hb3[c];
        out[g_rowmap[gwarp]] = 1.0f / (1.0f + expf(-s));
    }
}

// ---------------- launch ----------------
extern "C" void kernel_launch(void* const* d_in, const int* in_sizes, int n_in,
                              void* d_out, int out_size)
{
    const float* x     = (const float*)d_in[0];
    const int*   flags = (const int*)  d_in[1];
    const float* W1    = (const float*)d_in[2];
    const float* b1    = (const float*)d_in[3];
    const float* W2    = (const float*)d_in[4];
    const float* b2    = (const float*)d_in[5];
    const float* HW1   = (const float*)d_in[6];
    const float* Hb1   = (const float*)d_in[7];
    const float* HW2   = (const float*)d_in[8];
    const float* Hb2   = (const float*)d_in[9];
    const float* HW3   = (const float*)d_in[10];
    const float* Hb3   = (const float*)d_in[11];
    float* out = (float*)d_out;

    cudaFuncSetAttribute(gemm_mma<0, 0, 0, 0, 256, 1024>,
                         cudaFuncAttributeMaxDynamicSharedMemorySize, GEMM_SMEM);
    cudaFuncSetAttribute(gemm_mma<0, 1, 1, 1, 1024, 1024>,
                         cudaFuncAttributeMaxDynamicSharedMemorySize, GEMM_SMEM);
    cudaFuncSetAttribute(gemm_mma<1, 2, 2, 2, 1024, 512>,
                         cudaFuncAttributeMaxDynamicSharedMemorySize, GEMM_SMEM);
    cudaFuncSetAttribute(gemm_mma<2, 3, 3, 3, 512, 256>,
                         cudaFuncAttributeMaxDynamicSharedMemorySize, GEMM_SMEM);

    // prep
    partition_k<<<1, 1024>>>(flags);
    splitX_k<<<BATCH * 256 / 4 / 256, 256>>>(x);
    splitW_k<<<dim3(1024, 1, 4), 256>>>(W1, W2, HW1, HW2);

    // trunk L1: [16384,256] @ [256,1024] -> h1
    gemm_mma<0, 0, 0, 0, 256, 1024><<<dim3(8, 128, 1), GTHREADS, GEMM_SMEM>>>(b1);
    // trunk L2: [16384,1024] @ [1024,1024] -> h2
    gemm_mma<0, 1, 1, 1, 1024, 1024><<<dim3(8, 128, 1), GTHREADS, GEMM_SMEM>>>(b2);
    // head L1 (gather per-combo): [cnt_c,1024] @ HW1[c][1024,512] -> a1
    gemm_mma<1, 2, 2, 2, 1024, 512><<<dim3(4, 128, 4), GTHREADS, GEMM_SMEM>>>(Hb1);
    // head L2 (compact per-combo): [cnt_c,512] @ HW2[c][512,256] -> a2 fp32
    gemm_mma<2, 3, 3, 3, 512, 256><<<dim3(2, 128, 4), GTHREADS, GEMM_SMEM>>>(Hb2);

    head3_k<<<(BATCH * 32) / 256, 256>>>(HW3, Hb3, out);
}

// round 13
// speedup vs baseline: 2.5938x; 1.0276x over previous
#include <cuda_runtime.h>
#include <cuda_fp16.h>
#include <math.h>
#include <stdint.h>

#define BATCH 16384
#define KC 64                       // K elements per SMEM stage
#define STAGE_BYTES 32768           // A 16KB + B 16KB
#define A_OFF 0
#define B_OFF 16384
#define NSTAGE 3
#define GEMM_SMEM (NSTAGE * STAGE_BYTES)
#define GTHREADS 256
// fused head kernel: CTA 128x256, A 16KB + B 32KB
#define HSTAGE_BYTES 49152
#define HGEMM_SMEM (NSTAGE * HSTAGE_BYTES)
#define HTHREADS 512

// ---------------- scratch (no allocations allowed) ----------------
__device__ __half g_x[BATCH * 256];
__device__ __half g_h1[BATCH * 1024];
__device__ __half g_h2[BATCH * 1024];
__device__ __half g_a1[BATCH * 512];
// weights: fp16, transposed to K-major + pre-swizzled blocked tiles
// blocked layout: [c][nt=N/128][kt=K/64][8192 elems] (tile: n-row 0..127 x k 0..63,
// element (rr,kk) at byte swz(rr*128 + kk*2) within the 16KB tile)
__device__ __half g_w1[256 * 1024];
__device__ __half g_w2[1024 * 1024];
__device__ __half g_hw1[4 * 1024 * 512];
__device__ __half g_hw2[4 * 512 * 256];
__device__ int g_rowmap[BATCH];
__device__ int g_off[5];

// ---------------- helpers (baseline PTX only) ----------------
__device__ __forceinline__ uint32_t smem_u32(const void* p) {
    uint32_t a;
    asm("{ .reg .u64 t; cvta.to.shared.u64 t, %1; cvt.u32.u64 %0, t; }" : "=r"(a) : "l"(p));
    return a;
}
#define LDSM_X4(r0, r1, r2, r3, addr) \
    asm volatile("ldmatrix.sync.aligned.m8n8.x4.shared.b16 {%0,%1,%2,%3}, [%4];" \
                 : "=r"(r0), "=r"(r1), "=r"(r2), "=r"(r3) : "r"(addr))
#define CP16(dst, src) \
    asm volatile("cp.async.cg.shared.global [%0], [%1], 16;" :: "r"(dst), "l"(src) : "memory")
#define CP_COMMIT() asm volatile("cp.async.commit_group;" ::: "memory")
#define CP_WAIT1() asm volatile("cp.async.wait_group 1;" ::: "memory")
#define CP_WAIT0() asm volatile("cp.async.wait_group 0;" ::: "memory")

__device__ __forceinline__ void mma_fp16(float* d, const uint32_t* a, uint32_t b0, uint32_t b1) {
    asm volatile(
        "mma.sync.aligned.m16n8k16.row.col.f32.f16.f16.f32 "
        "{%0,%1,%2,%3}, {%4,%5,%6,%7}, {%8,%9}, {%0,%1,%2,%3};"
        : "+f"(d[0]), "+f"(d[1]), "+f"(d[2]), "+f"(d[3])
        : "r"(a[0]), "r"(a[1]), "r"(a[2]), "r"(a[3]), "r"(b0), "r"(b1));
}
__device__ __forceinline__ uint32_t pack2h(__half a, __half b) {
    return ((uint32_t)__half_as_ushort(b) << 16) | (uint32_t)__half_as_ushort(a);
}
__device__ __forceinline__ uint32_t swz(uint32_t off) { return off ^ ((off >> 3) & 0x70); }

// ---------------- prep: combo partitioning (one block, warp-aggregated) -------
__global__ void partition_k(const int* __restrict__ flags) {
    __shared__ int soff[4];
    const int tid = threadIdx.x;
    const int lane = tid & 31;

    if (tid < 4) soff[tid] = 0;
    __syncthreads();
    for (int i = tid; i < BATCH; i += 1024) {
        int c = flags[2 * i] * 2 + flags[2 * i + 1];
        unsigned same = __match_any_sync(0xFFFFFFFFu, c);
        int leader = __ffs(same) - 1;
        if (lane == leader) atomicAdd(&soff[c], __popc(same));
    }
    __syncthreads();
    if (tid == 0) {
        int o = 0;
        #pragma unroll
        for (int c = 0; c < 4; c++) { int n = soff[c]; g_off[c] = o; soff[c] = o; o += n; }
        g_off[4] = o;
    }
    __syncthreads();
    for (int i = tid; i < BATCH; i += 1024) {
        int c = flags[2 * i] * 2 + flags[2 * i + 1];
        unsigned same = __match_any_sync(0xFFFFFFFFu, c);
        int leader = __ffs(same) - 1;
        int rank = __popc(same & ((1u << lane) - 1u));
        int base = 0;
        if (lane == leader) base = atomicAdd(&soff[c], __popc(same));
        base = __shfl_sync(0xFFFFFFFFu, base, leader);
        g_rowmap[base + rank] = i;
    }
}

// ---------------- prep: convert x to fp16 ----------------
__global__ void splitX_k(const float* __restrict__ x) {
    int idx = blockIdx.x * blockDim.x + threadIdx.x;
    if (idx >= BATCH * 256 / 4) return;
    float4 v = *(const float4*)(x + (size_t)idx * 4);
    *(uint2*)(g_x + (size_t)idx * 4) =
        make_uint2(pack2h(__float2half_rn(v.x), __float2half_rn(v.y)),
                   pack2h(__float2half_rn(v.z), __float2half_rn(v.w)));
}

// ---------------- prep: convert + transpose + swizzle all weights (fp16) ------
__global__ void splitW_k(const float* __restrict__ W1, const float* __restrict__ W2,
                         const float* __restrict__ HW1, const float* __restrict__ HW2) {
    int z = blockIdx.z;
    int K, N, C;
    const float* src;
    __half* dh;
    if (z == 0)      { K = 256;  N = 1024; C = 1; src = W1;  dh = g_w1; }
    else if (z == 1) { K = 1024; N = 1024; C = 1; src = W2;  dh = g_w2; }
    else if (z == 2) { K = 1024; N = 512;  C = 4; src = HW1; dh = g_hw1; }
    else             { K = 512;  N = 256;  C = 4; src = HW2; dh = g_hw2; }
    const int kg = K >> 3;
    int idx = blockIdx.x * blockDim.x + threadIdx.x;
    if (idx >= C * N * kg) return;
    const int n_ = idx % N;
    const int t  = idx / N;
    const int k8 = (t % kg) * 8;
    const int c  = t / kg;

    const float* s = src + ((size_t)c * K + k8) * N + n_;
    __half hb[8];
    #pragma unroll
    for (int j = 0; j < 8; j++) hb[j] = __float2half_rn(s[(size_t)j * N]);

    const int nt = n_ >> 7, rr = n_ & 127, kt = k8 >> 6, kk = k8 & 63;
    const size_t base = (((size_t)c * (N >> 7) + nt) * (K >> 6) + kt) * 8192;
    const uint32_t sw = swz((uint32_t)rr * 128 + kk * 2);
    *(uint4*)((char*)(dh + base) + sw) = *(uint4*)hb;
}

// ---------------- warp-MMA fp16 GEMM + bias + relu (256 thr, 2 CTA/SM) --------
// CTA tile 128x128, 8 warps in 4(m) x 2(n) grid, warp tile 32x64.
// MODE: 0 dense, 1 gather via g_rowmap, 2 compact
// ASRC: 0 g_x, 1 g_h1, 2 g_h2
// WSRC: 0 w1, 1 w2, 2 hw1
// DST : 0 g_h1, 1 g_h2, 2 g_a1
template <int MODE, int ASRC, int WSRC, int DST, int K, int N>
__global__ __launch_bounds__(GTHREADS, 2)
void gemm_mma(const float* __restrict__ Bias)
{
    extern __shared__ __align__(1024) char smem[];
    constexpr int NK = K / KC;
    const int tid = threadIdx.x;
    const int c = blockIdx.z;

    int mstart, mend;
    if (MODE == 0) { mstart = 0; mend = BATCH; }
    else           { mstart = g_off[c]; mend = g_off[c + 1]; }
    const int m0 = mstart + blockIdx.y * 128;
    if (m0 >= mend) return;
    const int n0 = blockIdx.x * 128;

    const float* bc = Bias + (size_t)c * N;
    const uint32_t smb = smem_u32(smem);

    // ---- source pointers ----
    const __half* Ab;
    if (ASRC == 0)      Ab = g_x;
    else if (ASRC == 1) Ab = g_h1;
    else                Ab = g_h2;
    const __half* Wb;
    if (WSRC == 0)      Wb = g_w1;
    else if (WSRC == 1) Wb = g_w2;
    else                Wb = g_hw1;
    const __half* Wt = Wb + (((size_t)c * (N >> 7) + blockIdx.x) * (K >> 6)) * 8192;

    // ---- A loader mapping: 2 threads per row, 64B (32 elems) each ----
    const int ar = tid >> 1;          // 0..127
    const int aqe = (tid & 1) * 32;   // elem offset within row
    int apos = m0 + ar;
    if (apos > mend - 1) apos = mend - 1;
    const int grow = (MODE == 1) ? g_rowmap[apos] : apos;
    const __half* Ar = Ab + (size_t)grow * K + aqe;
    const uint32_t a_sw_base = (uint32_t)ar * 128 + aqe * 2;

    auto issue = [&](int kc) {
        const int s = kc % NSTAGE;
        const uint32_t stb = smb + s * STAGE_BYTES;
        const int k0 = kc * KC;
        #pragma unroll
        for (int j = 0; j < 4; j++) {
            uint32_t sw = swz(a_sw_base + j * 16);
            CP16(stb + A_OFF + sw, Ar + k0 + j * 8);
        }
        const __half* wh = Wt + (size_t)kc * 8192 + tid * 32;
        #pragma unroll
        for (int j = 0; j < 4; j++)
            CP16(stb + B_OFF + tid * 64 + j * 16, wh + j * 8);
        CP_COMMIT();
    };

    // ---- warp MMA state: 8 warps in 4(m) x 2(n) grid, warp tile 32x64 ----
    const int wid = tid >> 5;
    const int lane = tid & 31;
    const int wm = (wid & 3) * 32;
    const int wn = (wid >> 2) * 64;

    float acc[2][8][4];   // [m16 frag][n8 frag][quad regs]
    #pragma unroll
    for (int i = 0; i < 2; i++)
        #pragma unroll
        for (int j = 0; j < 8; j++)
            #pragma unroll
            for (int q = 0; q < 4; q++) acc[i][j][q] = 0.0f;

    const int mat = lane >> 3, rin = lane & 7;
    const int a_row = ((mat & 1) << 3) + rin;
    const int a_kh  = (mat >> 1) << 3;
    const int b_row = ((mat >> 1) << 3) + rin;
    const int b_kh  = (mat & 1) << 3;

    auto consume = [&](int s) {
        const uint32_t aSm = smb + s * STAGE_BYTES + A_OFF;
        const uint32_t bSm = smb + s * STAGE_BYTES + B_OFF;
        #pragma unroll
        for (int k16 = 0; k16 < KC / 16; k16++) {
            const int kh = k16 * 16;
            uint32_t ah[2][4], bh[4][4];
            #pragma unroll
            for (int mi = 0; mi < 2; mi++) {
                uint32_t sw = swz((uint32_t)(wm + mi * 16 + a_row) * 128 + (kh + a_kh) * 2);
                LDSM_X4(ah[mi][0], ah[mi][1], ah[mi][2], ah[mi][3], aSm + sw);
            }
            #pragma unroll
            for (int nf = 0; nf < 4; nf++) {
                uint32_t sw = swz((uint32_t)(wn + nf * 16 + b_row) * 128 + (kh + b_kh) * 2);
                LDSM_X4(bh[nf][0], bh[nf][1], bh[nf][2], bh[nf][3], bSm + sw);
            }
            #pragma unroll
            for (int mi = 0; mi < 2; mi++)
                #pragma unroll
                for (int nf = 0; nf < 4; nf++)
                    #pragma unroll
                    for (int nn = 0; nn < 2; nn++)
                        mma_fp16(acc[mi][nf * 2 + nn], ah[mi],
                                 bh[nf][nn * 2], bh[nf][nn * 2 + 1]);
        }
    };

    // ---- 3-stage pipeline ----
    issue(0); issue(1);
    for (int kc = 0; kc < NK; kc++) {
        if (kc + 2 < NK) { CP_WAIT1(); } else { CP_WAIT0(); }
        __syncthreads();
        if (kc + 2 < NK) issue(kc + 2);
        consume(kc % NSTAGE);
    }

    // ---- epilogue ----
    __half* Oh;
    if (DST == 0)      Oh = g_h1;
    else if (DST == 1) Oh = g_h2;
    else               Oh = g_a1;

    const int qrow = lane >> 2;
    const int qcol = (lane & 3) * 2;
    #pragma unroll
    for (int mi = 0; mi < 2; mi++) {
        #pragma unroll
        for (int half = 0; half < 2; half++) {
            const int m = m0 + wm + mi * 16 + qrow + half * 8;
            if (MODE != 0 && m >= mend) continue;
            #pragma unroll
            for (int nj = 0; nj < 8; nj++) {
                const int col = n0 + wn + nj * 8 + qcol;
                float v0 = acc[mi][nj][half * 2 + 0] + __ldg(bc + col);
                float v1 = acc[mi][nj][half * 2 + 1] + __ldg(bc + col + 1);
                v0 = fmaxf(v0, 0.0f); v1 = fmaxf(v1, 0.0f);
                *(uint32_t*)(Oh + (size_t)m * N + col) =
                    pack2h(__float2half_rn(v0), __float2half_rn(v1));
            }
        }
    }
}

// ---------------- fused head L2 GEMM + L3 dot + sigmoid + scatter -------------
// CTA tile 128x256 (full N), 512 thr, 16 warps 4(m)x4(n), warp tile 32x64.
// A = g_a1 compact rows (K=512), W = g_hw2 (2 n-tiles per combo).
__global__ __launch_bounds__(HTHREADS, 1)
void gemm_head(const float* __restrict__ Hb2,
               const float* __restrict__ HW3,
               const float* __restrict__ Hb3,
               float* __restrict__ out)
{
    extern __shared__ __align__(1024) char smem[];
    __shared__ float part[128][4];
    constexpr int K = 512, N = 256, NK = K / KC;
    const int tid = threadIdx.x;
    const int c = blockIdx.z;

    const int mstart = g_off[c], mend = g_off[c + 1];
    const int m0 = mstart + blockIdx.y * 128;
    if (m0 >= mend) return;

    const float* bc = Hb2 + (size_t)c * N;
    const float* w3 = HW3 + (size_t)c * N;
    const uint32_t smb = smem_u32(smem);

    // ---- A loader: 4 threads per row, 32B (16 elems) each ----
    const int ar = tid >> 2;
    const int aq = tid & 3;
    int apos = m0 + ar;
    if (apos > mend - 1) apos = mend - 1;
    const __half* Ar = g_a1 + (size_t)apos * K + aq * 16;
    const uint32_t a_sw_base = (uint32_t)ar * 128 + aq * 32;

    // ---- B loader: 2 n-tiles (hw2 layout [c][nt=2][kt=8][8192]) ----
    const int bht = tid >> 8;        // n-tile 0/1
    const int bt2 = tid & 255;
    const __half* WtB = g_hw2 + (((size_t)c * 2 + bht) * (K >> 6)) * 8192 + bt2 * 32;

    auto issue = [&](int kc) {
        const int s = kc % NSTAGE;
        const uint32_t stb = smb + s * HSTAGE_BYTES;
        const int k0 = kc * KC;
        #pragma unroll
        for (int j = 0; j < 2; j++) {
            uint32_t sw = swz(a_sw_base + j * 16);
            CP16(stb + A_OFF + sw, Ar + k0 + j * 8);
        }
        const __half* wh = WtB + (size_t)kc * 8192;
        #pragma unroll
        for (int j = 0; j < 2; j++)
            CP16(stb + B_OFF + bht * 16384 + bt2 * 64 + j * 16, wh + j * 8);
        CP_COMMIT();
    };
    // note: per-thread B copy is 32B (2xCP16); 512 threads cover 16KB... need 32KB!
    // 512 thr x 64B = 32KB -> 4 CP16 per thread: fix inside issue2 below.

    const int wid = tid >> 5;
    const int lane = tid & 31;
    const int wm = (wid & 3) * 32;
    const int wn = (wid >> 2) * 64;

    float acc[2][8][4];
    #pragma unroll
    for (int i = 0; i < 2; i++)
        #pragma unroll
        for (int j = 0; j < 8; j++)
            #pragma unroll
            for (int q = 0; q < 4; q++) acc[i][j][q] = 0.0f;

    const int mat = lane >> 3, rin = lane & 7;
    const int a_row = ((mat & 1) << 3) + rin;
    const int a_kh  = (mat >> 1) << 3;
    const int b_row = ((mat >> 1) << 3) + rin;
    const int b_kh  = (mat & 1) << 3;

    auto consume = [&](int s) {
        const uint32_t aSm = smb + s * HSTAGE_BYTES + A_OFF;
        const uint32_t bSm = smb + s * HSTAGE_BYTES + B_OFF;
        #pragma unroll
        for (int k16 = 0; k16 < KC / 16; k16++) {
            const int kh = k16 * 16;
            uint32_t ah[2][4], bh[4][4];
            #pragma unroll
            for (int mi = 0; mi < 2; mi++) {
                uint32_t sw = swz((uint32_t)(wm + mi * 16 + a_row) * 128 + (kh + a_kh) * 2);
                LDSM_X4(ah[mi][0], ah[mi][1], ah[mi][2], ah[mi][3], aSm + sw);
            }
            #pragma unroll
            for (int nf = 0; nf < 4; nf++) {
                const int colb = wn + nf * 16;
                uint32_t base = bSm + (colb >> 7) * 16384;
                uint32_t sw = swz((uint32_t)((colb & 127) + b_row) * 128 + (kh + b_kh) * 2);
                LDSM_X4(bh[nf][0], bh[nf][1], bh[nf][2], bh[nf][3], base + sw);
            }
            #pragma unroll
            for (int mi = 0; mi < 2; mi++)
                #pragma unroll
                for (int nf = 0; nf < 4; nf++)
                    #pragma unroll
                    for (int nn = 0; nn < 2; nn++)
                        mma_fp16(acc[mi][nf * 2 + nn], ah[mi],
                                 bh[nf][nn * 2], bh[nf][nn * 2 + 1]);
        }
    };

    // B copy actually needs 64B/thread: redo issue with 4 CP16 on B
    auto issue2 = [&](int kc) {
        const int s = kc % NSTAGE;
        const uint32_t stb = smb + s * HSTAGE_BYTES;
        const int k0 = kc * KC;
        #pragma unroll
        for (int j = 0; j < 2; j++) {
            uint32_t sw = swz(a_sw_base + j * 16);
            CP16(stb + A_OFF + sw, Ar + k0 + j * 8);
        }
        // 512 threads, 32KB B: thread covers 64B of one tile: retile mapping
        const int h2 = tid >> 8;        // tile
        const int t4 = tid & 255;       // 256 thr x 64B = 16KB per tile... x2 tiles = 32KB ok
        const __half* wh = g_hw2 + ((((size_t)c * 2 + h2) * (K >> 6)) + kc) * 8192 + t4 * 32;
        #pragma unroll
        for (int j = 0; j < 4; j++)
            CP16(stb + B_OFF + h2 * 16384 + t4 * 64 + j * 16, wh + j * 8);
        CP_COMMIT();
    };
    (void)issue;

    issue2(0); issue2(1);
    for (int kc = 0; kc < NK; kc++) {
        if (kc + 2 < NK) { CP_WAIT1(); } else { CP_WAIT0(); }
        __syncthreads();
        if (kc + 2 < NK) issue2(kc + 2);
        consume(kc % NSTAGE);
    }

    // ---- fused epilogue: relu(+Hb2) dot HW3 -> sigmoid -> scatter ----
    const int qrow = lane >> 2;
    const int qcol = (lane & 3) * 2;
    float psum[2][2];
    #pragma unroll
    for (int mi = 0; mi < 2; mi++)
        #pragma unroll
        for (int half = 0; half < 2; half++) {
            float p = 0.0f;
            #pragma unroll
            for (int nj = 0; nj < 8; nj++) {
                const int col = wn + nj * 8 + qcol;
                float v0 = fmaxf(acc[mi][nj][half * 2 + 0] + __ldg(bc + col), 0.0f);
                float v1 = fmaxf(acc[mi][nj][half * 2 + 1] + __ldg(bc + col + 1), 0.0f);
                p = fmaf(v0, __ldg(w3 + col), p);
                p = fmaf(v1, __ldg(w3 + col + 1), p);
            }
            psum[mi][half] = p;
        }
    // quad reduce (lanes qrow*4 .. qrow*4+3 share a row)
    #pragma unroll
    for (int mi = 0; mi < 2; mi++)
        #pragma unroll
        for (int half = 0; half < 2; half++) {
            float p = psum[mi][half];
            p += __shfl_xor_sync(0xFFFFFFFFu, p, 1);
            p += __shfl_xor_sync(0xFFFFFFFFu, p, 2);
            psum[mi][half] = p;
        }
    if ((lane & 3) == 0) {
        #pragma unroll
        for (int mi = 0; mi < 2; mi++)
            #pragma unroll
            for (int half = 0; half < 2; half++)
                part[wm + mi * 16 + qrow + half * 8][wid >> 2] = psum[mi][half];
    }
    __syncthreads();
    if (tid < 128) {
        const int m = m0 + tid;
        if (m < mend) {
            float s = part[tid][0] + part[tid][1] + part[tid][2] + part[tid][3]
                    + __ldg(Hb3 + c);
            out[g_rowmap[m]] = 1.0f / (1.0f + expf(-s));
        }
    }
}

// ---------------- launch ----------------
extern "C" void kernel_launch(void* const* d_in, const int* in_sizes, int n_in,
                              void* d_out, int out_size)
{
    const float* x     = (const float*)d_in[0];
    const int*   flags = (const int*)  d_in[1];
    const float* W1    = (const float*)d_in[2];
    const float* b1    = (const float*)d_in[3];
    const float* W2    = (const float*)d_in[4];
    const float* b2    = (const float*)d_in[5];
    const float* HW1   = (const float*)d_in[6];
    const float* Hb1   = (const float*)d_in[7];
    const float* HW2   = (const float*)d_in[8];
    const float* Hb2   = (const float*)d_in[9];
    const float* HW3   = (const float*)d_in[10];
    const float* Hb3   = (const float*)d_in[11];
    float* out = (float*)d_out;

    cudaFuncSetAttribute(gemm_mma<0, 0, 0, 0, 256, 1024>,
                         cudaFuncAttributeMaxDynamicSharedMemorySize, GEMM_SMEM);
    cudaFuncSetAttribute(gemm_mma<0, 1, 1, 1, 1024, 1024>,
                         cudaFuncAttributeMaxDynamicSharedMemorySize, GEMM_SMEM);
    cudaFuncSetAttribute(gemm_mma<1, 2, 2, 2, 1024, 512>,
                         cudaFuncAttributeMaxDynamicSharedMemorySize, GEMM_SMEM);
    cudaFuncSetAttribute(gemm_head,
                         cudaFuncAttributeMaxDynamicSharedMemorySize, HGEMM_SMEM);

    // prep
    partition_k<<<1, 1024>>>(flags);
    splitX_k<<<BATCH * 256 / 4 / 256, 256>>>(x);
    splitW_k<<<dim3(1024, 1, 4), 256>>>(W1, W2, HW1, HW2);

    // trunk L1: [16384,256] @ [256,1024] -> h1
    gemm_mma<0, 0, 0, 0, 256, 1024><<<dim3(8, 128, 1), GTHREADS, GEMM_SMEM>>>(b1);
    // trunk L2: [16384,1024] @ [1024,1024] -> h2
    gemm_mma<0, 1, 1, 1, 1024, 1024><<<dim3(8, 128, 1), GTHREADS, GEMM_SMEM>>>(b2);
    // head L1 (gather per-combo): [cnt_c,1024] @ HW1[c][1024,512] -> a1
    gemm_mma<1, 2, 2, 2, 1024, 512><<<dim3(4, 128, 4), GTHREADS, GEMM_SMEM>>>(Hb1);
    // head L2+L3 fused: [cnt_c,512] @ HW2[c] -> relu -> dot HW3[c] -> sigmoid -> out
    gemm_head<<<dim3(1, 128, 4), HTHREADS, HGEMM_SMEM>>>(Hb2, HW3, Hb3, out);
}

// round 14
// speedup vs baseline: 2.7167x; 1.0474x over previous
#include <cuda_runtime.h>
#include <cuda_fp16.h>
#include <math.h>
#include <stdint.h>

#define BATCH 16384
#define KC 64                       // K elements per SMEM stage
#define STAGE_BYTES 32768           // A 16KB + B 16KB
#define A_OFF 0
#define B_OFF 16384
#define NSTAGE 3
#define GEMM_SMEM (NSTAGE * STAGE_BYTES)
#define GTHREADS 256
// fused head kernel: CTA 128x256, A 16KB + B 32KB
#define HSTAGE_BYTES 49152
#define HGEMM_SMEM (NSTAGE * HSTAGE_BYTES)
#define HTHREADS 512

// ---------------- scratch (no allocations allowed) ----------------
__device__ __half g_x[BATCH * 256];
__device__ __half g_h1[BATCH * 1024];
__device__ __half g_h2[BATCH * 1024];
__device__ __half g_a1[BATCH * 512];
// weights: fp16, transposed to K-major + pre-swizzled blocked tiles
// blocked layout: [c][nt=N/128][kt=K/64][8192 elems]
__device__ __half g_w1[256 * 1024];
__device__ __half g_w2[1024 * 1024];
__device__ __half g_hw1[4 * 1024 * 512];
__device__ __half g_hw2[4 * 512 * 256];
__device__ int g_rowmap[BATCH];
__device__ int g_off[5];

// ---------------- static streams/events for graph fork-join -------------------
struct _GraphStreams {
    cudaStream_t side;
    cudaEvent_t fork, join;
    _GraphStreams() {
        cudaStreamCreateWithFlags(&side, cudaStreamNonBlocking);
        cudaEventCreateWithFlags(&fork, cudaEventDisableTiming);
        cudaEventCreateWithFlags(&join, cudaEventDisableTiming);
    }
};
static _GraphStreams g_gs;

// ---------------- helpers (baseline PTX only) ----------------
__device__ __forceinline__ uint32_t smem_u32(const void* p) {
    uint32_t a;
    asm("{ .reg .u64 t; cvta.to.shared.u64 t, %1; cvt.u32.u64 %0, t; }" : "=r"(a) : "l"(p));
    return a;
}
#define LDSM_X4(r0, r1, r2, r3, addr) \
    asm volatile("ldmatrix.sync.aligned.m8n8.x4.shared.b16 {%0,%1,%2,%3}, [%4];" \
                 : "=r"(r0), "=r"(r1), "=r"(r2), "=r"(r3) : "r"(addr))
#define CP16(dst, src) \
    asm volatile("cp.async.cg.shared.global [%0], [%1], 16;" :: "r"(dst), "l"(src) : "memory")
#define CP_COMMIT() asm volatile("cp.async.commit_group;" ::: "memory")
#define CP_WAIT1() asm volatile("cp.async.wait_group 1;" ::: "memory")
#define CP_WAIT0() asm volatile("cp.async.wait_group 0;" ::: "memory")

__device__ __forceinline__ void mma_fp16(float* d, const uint32_t* a, uint32_t b0, uint32_t b1) {
    asm volatile(
        "mma.sync.aligned.m16n8k16.row.col.f32.f16.f16.f32 "
        "{%0,%1,%2,%3}, {%4,%5,%6,%7}, {%8,%9}, {%0,%1,%2,%3};"
        : "+f"(d[0]), "+f"(d[1]), "+f"(d[2]), "+f"(d[3])
        : "r"(a[0]), "r"(a[1]), "r"(a[2]), "r"(a[3]), "r"(b0), "r"(b1));
}
__device__ __forceinline__ uint32_t pack2h(__half a, __half b) {
    return ((uint32_t)__half_as_ushort(b) << 16) | (uint32_t)__half_as_ushort(a);
}
__device__ __forceinline__ uint32_t swz(uint32_t off) { return off ^ ((off >> 3) & 0x70); }

// ---------------- splitW worker: one 8-deep k-column of one weight matrix -----
__device__ __forceinline__ void splitW_item(const float* __restrict__ src, __half* __restrict__ dh,
                                            int K, int N, int idx) {
    const int kg = K >> 3;
    const int n_ = idx % N;
    const int t  = idx / N;
    const int k8 = (t % kg) * 8;
    const int c  = t / kg;

    const float* s = src + ((size_t)c * K + k8) * N + n_;
    __half hb[8];
    #pragma unroll
    for (int j = 0; j < 8; j++) hb[j] = __float2half_rn(s[(size_t)j * N]);

    const int nt = n_ >> 7, rr = n_ & 127, kt = k8 >> 6, kk = k8 & 63;
    const size_t base = (((size_t)c * (N >> 7) + nt) * (K >> 6) + kt) * 8192;
    const uint32_t sw = swz((uint32_t)rr * 128 + kk * 2);
    *(uint4*)((char*)(dh + base) + sw) = *(uint4*)hb;
}

// ---------------- main-stream prep: splitX + convert W1/W2 --------------------
// blocks [0,1024): splitX (4 floats/thread); [1024,1184): W1 (32768 items) then W2 (131072)
__global__ void prep_main_k(const float* __restrict__ x,
                            const float* __restrict__ W1, const float* __restrict__ W2) {
    const int b = blockIdx.x;
    const int tid = threadIdx.x;
    if (b < 1024) {
        int idx = b * 1024 + tid;
        float4 v = *(const float4*)(x + (size_t)idx * 4);
        *(uint2*)(g_x + (size_t)idx * 4) =
            make_uint2(pack2h(__float2half_rn(v.x), __float2half_rn(v.y)),
                       pack2h(__float2half_rn(v.z), __float2half_rn(v.w)));
    } else {
        int widx = (b - 1024) * 1024 + tid;
        if (widx < 32768)       splitW_item(W1, g_w1, 256, 1024, widx);
        else if (widx < 163840) splitW_item(W2, g_w2, 1024, 1024, widx - 32768);
    }
}

// ---------------- side-stream prep: partition + convert HW1/HW2 ---------------
// block 0: partition; blocks [1,321): HW1 (262144 items) then HW2 (65536)
__global__ void prep_side_k(const int* __restrict__ flags,
                            const float* __restrict__ HW1, const float* __restrict__ HW2) {
    const int b = blockIdx.x;
    const int tid = threadIdx.x;
    if (b == 0) {
        __shared__ int soff[4];
        const int lane = tid & 31;
        if (tid < 4) soff[tid] = 0;
        __syncthreads();
        for (int i = tid; i < BATCH; i += 1024) {
            int c = flags[2 * i] * 2 + flags[2 * i + 1];
            unsigned same = __match_any_sync(0xFFFFFFFFu, c);
            int leader = __ffs(same) - 1;
            if (lane == leader) atomicAdd(&soff[c], __popc(same));
        }
        __syncthreads();
        if (tid == 0) {
            int o = 0;
            #pragma unroll
            for (int c = 0; c < 4; c++) { int n = soff[c]; g_off[c] = o; soff[c] = o; o += n; }
            g_off[4] = o;
        }
        __syncthreads();
        for (int i = tid; i < BATCH; i += 1024) {
            int c = flags[2 * i] * 2 + flags[2 * i + 1];
            unsigned same = __match_any_sync(0xFFFFFFFFu, c);
            int leader = __ffs(same) - 1;
            int rank = __popc(same & ((1u << lane) - 1u));
            int base = 0;
            if (lane == leader) base = atomicAdd(&soff[c], __popc(same));
            base = __shfl_sync(0xFFFFFFFFu, base, leader);
            g_rowmap[base + rank] = i;
        }
    } else {
        int widx = (b - 1) * 1024 + tid;
        if (widx < 262144)      splitW_item(HW1, g_hw1, 1024, 512, widx);
        else if (widx < 327680) splitW_item(HW2, g_hw2, 512, 256, widx - 262144);
    }
}

// ---------------- warp-MMA fp16 GEMM + bias + relu (256 thr, 2 CTA/SM) --------
// CTA tile 128x128, 8 warps in 4(m) x 2(n) grid, warp tile 32x64.
// MODE: 0 dense, 1 gather via g_rowmap
// ASRC: 0 g_x, 1 g_h1, 2 g_h2 / WSRC: 0 w1, 1 w2, 2 hw1 / DST: 0 g_h1, 1 g_h2, 2 g_a1
template <int MODE, int ASRC, int WSRC, int DST, int K, int N>
__global__ __launch_bounds__(GTHREADS, 2)
void gemm_mma(const float* __restrict__ Bias)
{
    extern __shared__ __align__(1024) char smem[];
    constexpr int NK = K / KC;
    const int tid = threadIdx.x;
    const int c = blockIdx.z;

    int mstart, mend;
    if (MODE == 0) { mstart = 0; mend = BATCH; }
    else           { mstart = g_off[c]; mend = g_off[c + 1]; }
    const int m0 = mstart + blockIdx.y * 128;
    if (m0 >= mend) return;
    const int n0 = blockIdx.x * 128;

    const float* bc = Bias + (size_t)c * N;
    const uint32_t smb = smem_u32(smem);

    const __half* Ab;
    if (ASRC == 0)      Ab = g_x;
    else if (ASRC == 1) Ab = g_h1;
    else                Ab = g_h2;
    const __half* Wb;
    if (WSRC == 0)      Wb = g_w1;
    else if (WSRC == 1) Wb = g_w2;
    else                Wb = g_hw1;
    const __half* Wt = Wb + (((size_t)c * (N >> 7) + blockIdx.x) * (K >> 6)) * 8192;

    const int ar = tid >> 1;
    const int aqe = (tid & 1) * 32;
    int apos = m0 + ar;
    if (apos > mend - 1) apos = mend - 1;
    const int grow = (MODE == 1) ? g_rowmap[apos] : apos;
    const __half* Ar = Ab + (size_t)grow * K + aqe;
    const uint32_t a_sw_base = (uint32_t)ar * 128 + aqe * 2;

    auto issue = [&](int kc) {
        const int s = kc % NSTAGE;
        const uint32_t stb = smb + s * STAGE_BYTES;
        const int k0 = kc * KC;
        #pragma unroll
        for (int j = 0; j < 4; j++) {
            uint32_t sw = swz(a_sw_base + j * 16);
            CP16(stb + A_OFF + sw, Ar + k0 + j * 8);
        }
        const __half* wh = Wt + (size_t)kc * 8192 + tid * 32;
        #pragma unroll
        for (int j = 0; j < 4; j++)
            CP16(stb + B_OFF + tid * 64 + j * 16, wh + j * 8);
        CP_COMMIT();
    };

    const int wid = tid >> 5;
    const int lane = tid & 31;
    const int wm = (wid & 3) * 32;
    const int wn = (wid >> 2) * 64;

    float acc[2][8][4];
    #pragma unroll
    for (int i = 0; i < 2; i++)
        #pragma unroll
        for (int j = 0; j < 8; j++)
            #pragma unroll
            for (int q = 0; q < 4; q++) acc[i][j][q] = 0.0f;

    const int mat = lane >> 3, rin = lane & 7;
    const int a_row = ((mat & 1) << 3) + rin;
    const int a_kh  = (mat >> 1) << 3;
    const int b_row = ((mat >> 1) << 3) + rin;
    const int b_kh  = (mat & 1) << 3;

    auto consume = [&](int s) {
        const uint32_t aSm = smb + s * STAGE_BYTES + A_OFF;
        const uint32_t bSm = smb + s * STAGE_BYTES + B_OFF;
        #pragma unroll
        for (int k16 = 0; k16 < KC / 16; k16++) {
            const int kh = k16 * 16;
            uint32_t ah[2][4], bh[4][4];
            #pragma unroll
            for (int mi = 0; mi < 2; mi++) {
                uint32_t sw = swz((uint32_t)(wm + mi * 16 + a_row) * 128 + (kh + a_kh) * 2);
                LDSM_X4(ah[mi][0], ah[mi][1], ah[mi][2], ah[mi][3], aSm + sw);
            }
            #pragma unroll
            for (int nf = 0; nf < 4; nf++) {
                uint32_t sw = swz((uint32_t)(wn + nf * 16 + b_row) * 128 + (kh + b_kh) * 2);
                LDSM_X4(bh[nf][0], bh[nf][1], bh[nf][2], bh[nf][3], bSm + sw);
            }
            #pragma unroll
            for (int mi = 0; mi < 2; mi++)
                #pragma unroll
                for (int nf = 0; nf < 4; nf++)
                    #pragma unroll
                    for (int nn = 0; nn < 2; nn++)
                        mma_fp16(acc[mi][nf * 2 + nn], ah[mi],
                                 bh[nf][nn * 2], bh[nf][nn * 2 + 1]);
        }
    };

    issue(0); issue(1);
    for (int kc = 0; kc < NK; kc++) {
        if (kc + 2 < NK) { CP_WAIT1(); } else { CP_WAIT0(); }
        __syncthreads();
        if (kc + 2 < NK) issue(kc + 2);
        consume(kc % NSTAGE);
    }

    __half* Oh;
    if (DST == 0)      Oh = g_h1;
    else if (DST == 1) Oh = g_h2;
    else               Oh = g_a1;

    const int qrow = lane >> 2;
    const int qcol = (lane & 3) * 2;
    #pragma unroll
    for (int mi = 0; mi < 2; mi++) {
        #pragma unroll
        for (int half = 0; half < 2; half++) {
            const int m = m0 + wm + mi * 16 + qrow + half * 8;
            if (MODE != 0 && m >= mend) continue;
            #pragma unroll
            for (int nj = 0; nj < 8; nj++) {
                const int col = n0 + wn + nj * 8 + qcol;
                float v0 = acc[mi][nj][half * 2 + 0] + __ldg(bc + col);
                float v1 = acc[mi][nj][half * 2 + 1] + __ldg(bc + col + 1);
                v0 = fmaxf(v0, 0.0f); v1 = fmaxf(v1, 0.0f);
                *(uint32_t*)(Oh + (size_t)m * N + col) =
                    pack2h(__float2half_rn(v0), __float2half_rn(v1));
            }
        }
    }
}

// ---------------- fused head L2 GEMM + L3 dot + sigmoid + scatter -------------
__global__ __launch_bounds__(HTHREADS, 1)
void gemm_head(const float* __restrict__ Hb2,
               const float* __restrict__ HW3,
               const float* __restrict__ Hb3,
               float* __restrict__ out)
{
    extern __shared__ __align__(1024) char smem[];
    __shared__ float part[128][4];
    constexpr int K = 512, N = 256, NK = K / KC;
    const int tid = threadIdx.x;
    const int c = blockIdx.z;

    const int mstart = g_off[c], mend = g_off[c + 1];
    const int m0 = mstart + blockIdx.y * 128;
    if (m0 >= mend) return;

    const float* bc = Hb2 + (size_t)c * N;
    const float* w3 = HW3 + (size_t)c * N;
    const uint32_t smb = smem_u32(smem);

    const int ar = tid >> 2;
    const int aq = tid & 3;
    int apos = m0 + ar;
    if (apos > mend - 1) apos = mend - 1;
    const __half* Ar = g_a1 + (size_t)apos * K + aq * 16;
    const uint32_t a_sw_base = (uint32_t)ar * 128 + aq * 32;

    const int wid = tid >> 5;
    const int lane = tid & 31;
    const int wm = (wid & 3) * 32;
    const int wn = (wid >> 2) * 64;

    float acc[2][8][4];
    #pragma unroll
    for (int i = 0; i < 2; i++)
        #pragma unroll
        for (int j = 0; j < 8; j++)
            #pragma unroll
            for (int q = 0; q < 4; q++) acc[i][j][q] = 0.0f;

    const int mat = lane >> 3, rin = lane & 7;
    const int a_row = ((mat & 1) << 3) + rin;
    const int a_kh  = (mat >> 1) << 3;
    const int b_row = ((mat >> 1) << 3) + rin;
    const int b_kh  = (mat & 1) << 3;

    auto consume = [&](int s) {
        const uint32_t aSm = smb + s * HSTAGE_BYTES + A_OFF;
        const uint32_t bSm = smb + s * HSTAGE_BYTES + B_OFF;
        #pragma unroll
        for (int k16 = 0; k16 < KC / 16; k16++) {
            const int kh = k16 * 16;
            uint32_t ah[2][4], bh[4][4];
            #pragma unroll
            for (int mi = 0; mi < 2; mi++) {
                uint32_t sw = swz((uint32_t)(wm + mi * 16 + a_row) * 128 + (kh + a_kh) * 2);
                LDSM_X4(ah[mi][0], ah[mi][1], ah[mi][2], ah[mi][3], aSm + sw);
            }
            #pragma unroll
            for (int nf = 0; nf < 4; nf++) {
                const int colb = wn + nf * 16;
                uint32_t base = bSm + (colb >> 7) * 16384;
                uint32_t sw = swz((uint32_t)((colb & 127) + b_row) * 128 + (kh + b_kh) * 2);
                LDSM_X4(bh[nf][0], bh[nf][1], bh[nf][2], bh[nf][3], base + sw);
            }
            #pragma unroll
            for (int mi = 0; mi < 2; mi++)
                #pragma unroll
                for (int nf = 0; nf < 4; nf++)
                    #pragma unroll
                    for (int nn = 0; nn < 2; nn++)
                        mma_fp16(acc[mi][nf * 2 + nn], ah[mi],
                                 bh[nf][nn * 2], bh[nf][nn * 2 + 1]);
        }
    };

    auto issue2 = [&](int kc) {
        const int s = kc % NSTAGE;
        const uint32_t stb = smb + s * HSTAGE_BYTES;
        const int k0 = kc * KC;
        #pragma unroll
        for (int j = 0; j < 2; j++) {
            uint32_t sw = swz(a_sw_base + j * 16);
            CP16(stb + A_OFF + sw, Ar + k0 + j * 8);
        }
        const int h2 = tid >> 8;
        const int t4 = tid & 255;
        const __half* wh = g_hw2 + ((((size_t)c * 2 + h2) * (K >> 6)) + kc) * 8192 + t4 * 32;
        #pragma unroll
        for (int j = 0; j < 4; j++)
            CP16(stb + B_OFF + h2 * 16384 + t4 * 64 + j * 16, wh + j * 8);
        CP_COMMIT();
    };

    issue2(0); issue2(1);
    for (int kc = 0; kc < NK; kc++) {
        if (kc + 2 < NK) { CP_WAIT1(); } else { CP_WAIT0(); }
        __syncthreads();
        if (kc + 2 < NK) issue2(kc + 2);
        consume(kc % NSTAGE);
    }

    const int qrow = lane >> 2;
    const int qcol = (lane & 3) * 2;
    float psum[2][2];
    #pragma unroll
    for (int mi = 0; mi < 2; mi++)
        #pragma unroll
        for (int half = 0; half < 2; half++) {
            float p = 0.0f;
            #pragma unroll
            for (int nj = 0; nj < 8; nj++) {
                const int col = wn + nj * 8 + qcol;
                float v0 = fmaxf(acc[mi][nj][half * 2 + 0] + __ldg(bc + col), 0.0f);
                float v1 = fmaxf(acc[mi][nj][half * 2 + 1] + __ldg(bc + col + 1), 0.0f);
                p = fmaf(v0, __ldg(w3 + col), p);
                p = fmaf(v1, __ldg(w3 + col + 1), p);
            }
            psum[mi][half] = p;
        }
    #pragma unroll
    for (int mi = 0; mi < 2; mi++)
        #pragma unroll
        for (int half = 0; half < 2; half++) {
            float p = psum[mi][half];
            p += __shfl_xor_sync(0xFFFFFFFFu, p, 1);
            p += __shfl_xor_sync(0xFFFFFFFFu, p, 2);
            psum[mi][half] = p;
        }
    if ((lane & 3) == 0) {
        #pragma unroll
        for (int mi = 0; mi < 2; mi++)
            #pragma unroll
            for (int half = 0; half < 2; half++)
                part[wm + mi * 16 + qrow + half * 8][wid >> 2] = psum[mi][half];
    }
    __syncthreads();
    if (tid < 128) {
        const int m = m0 + tid;
        if (m < mend) {
            float s = part[tid][0] + part[tid][1] + part[tid][2] + part[tid][3]
                    + __ldg(Hb3 + c);
            out[g_rowmap[m]] = 1.0f / (1.0f + expf(-s));
        }
    }
}

// ---------------- launch ----------------
extern "C" void kernel_launch(void* const* d_in, const int* in_sizes, int n_in,
                              void* d_out, int out_size)
{
    const float* x     = (const float*)d_in[0];
    const int*   flags = (const int*)  d_in[1];
    const float* W1    = (const float*)d_in[2];
    const float* b1    = (const float*)d_in[3];
    const float* W2    = (const float*)d_in[4];
    const float* b2    = (const float*)d_in[5];
    const float* HW1   = (const float*)d_in[6];
    const float* Hb1   = (const float*)d_in[7];
    const float* HW2   = (const float*)d_in[8];
    const float* Hb2   = (const float*)d_in[9];
    const float* HW3   = (const float*)d_in[10];
    const float* Hb3   = (const float*)d_in[11];
    float* out = (float*)d_out;

    cudaFuncSetAttribute(gemm_mma<0, 0, 0, 0, 256, 1024>,
                         cudaFuncAttributeMaxDynamicSharedMemorySize, GEMM_SMEM);
    cudaFuncSetAttribute(gemm_mma<0, 1, 1, 1, 1024, 1024>,
                         cudaFuncAttributeMaxDynamicSharedMemorySize, GEMM_SMEM);
    cudaFuncSetAttribute(gemm_mma<1, 2, 2, 2, 1024, 512>,
                         cudaFuncAttributeMaxDynamicSharedMemorySize, GEMM_SMEM);
    cudaFuncSetAttribute(gemm_head,
                         cudaFuncAttributeMaxDynamicSharedMemorySize, HGEMM_SMEM);

    // fork: side stream does partition + HW1/HW2 conversion, overlapping gemm1/2
    cudaEventRecord(g_gs.fork, 0);
    cudaStreamWaitEvent(g_gs.side, g_gs.fork, 0);
    prep_side_k<<<321, 1024, 0, g_gs.side>>>(flags, HW1, HW2);
    cudaEventRecord(g_gs.join, g_gs.side);

    // main stream: splitX + W1/W2 conversion, then trunk gemms
    prep_main_k<<<1184, 1024>>>(x, W1, W2);
    // trunk L1: [16384,256] @ [256,1024] -> h1
    gemm_mma<0, 0, 0, 0, 256, 1024><<<dim3(8, 128, 1), GTHREADS, GEMM_SMEM>>>(b1);
    // trunk L2: [16384,1024] @ [1024,1024] -> h2
    gemm_mma<0, 1, 1, 1, 1024, 1024><<<dim3(8, 128, 1), GTHREADS, GEMM_SMEM>>>(b2);

    // join: gemm3 needs rowmap + hw1; head needs hw2
    cudaStreamWaitEvent(0, g_gs.join, 0);
    // head L1 (gather per-combo): [cnt_c,1024] @ HW1[c][1024,512] -> a1
    gemm_mma<1, 2, 2, 2, 1024, 512><<<dim3(4, 128, 4), GTHREADS, GEMM_SMEM>>>(Hb1);
    // head L2+L3 fused: [cnt_c,512] @ HW2[c] -> relu -> dot HW3[c] -> sigmoid -> out
    gemm_head<<<dim3(1, 128, 4), HTHREADS, HGEMM_SMEM>>>(Hb2, HW3, Hb3, out);
}